// round 1
// baseline (speedup 1.0000x reference)
#include <cuda_runtime.h>
#include <math.h>

#define Bv   2048
#define Lv   75
#define Ev   300
#define Hv   300
#define Kv   300
#define G3   900
#define OUTv 5

// ---------------- scratch (device globals; no allocation allowed) ----------
__device__ float d_gx[Lv * Bv * G3];     // (L, B, 3H) pre-computed input gates
__device__ float d_Hall[Lv * Bv * Hv];   // (L, B, H) hidden states
__device__ float d_gh[Bv * G3];          // per-step gh scratch
__device__ float d_h0[Bv * Hv];          // zero-initialized, never written => h(-1)=0

// ---------------------------------------------------------------------------
// Tiled SGEMM: out[m, n] = sum_k A[m,k] * W[n,k] + bias[n]
//   A rows: if idx != nullptr, row m -> emb[idx[(m%B)*L + m/B]] (embedding gather,
//   time-major row order m = l*B + b); else A row m -> A + m*K.
//   N = 900, K = 300 fixed. BM=BN=64, BK=16, 256 threads, 4x4 per thread.
// ---------------------------------------------------------------------------
__global__ void gemm_k(const float* __restrict__ A, const int* __restrict__ idx,
                       const float* __restrict__ W, const float* __restrict__ bias,
                       float* __restrict__ out, int M)
{
    const int N = G3, K = Kv;
    __shared__ float As[16][64];
    __shared__ float Bs[16][68];   // pad to soften bank conflicts

    int tid = threadIdx.x;
    int tx = tid & 15, ty = tid >> 4;
    int m0 = blockIdx.y * 64;
    int n0 = blockIdx.x * 64;

    float acc[4][4];
#pragma unroll
    for (int r = 0; r < 4; r++)
#pragma unroll
        for (int c = 0; c < 4; c++) acc[r][c] = 0.f;

    for (int k0 = 0; k0 < K; k0 += 16) {
        // load A tile (64 rows x 16 k)
#pragma unroll
        for (int i = 0; i < 4; i++) {
            int li = tid + i * 256;
            int ml = li >> 4, kk = li & 15;
            int m = m0 + ml, k = k0 + kk;
            float v = 0.f;
            if (m < M && k < K) {
                long base;
                if (idx) {
                    int l = m / Bv, bb = m % Bv;
                    base = (long)idx[bb * Lv + l] * Ev;
                } else {
                    base = (long)m * K;
                }
                v = A[base + k];
            }
            As[kk][ml] = v;
        }
        // load B tile (64 n x 16 k), W is (N, K) row-major
#pragma unroll
        for (int i = 0; i < 4; i++) {
            int li = tid + i * 256;
            int nl = li >> 4, kk = li & 15;
            int n = n0 + nl, k = k0 + kk;
            float v = (n < N && k < K) ? W[(long)n * K + k] : 0.f;
            Bs[kk][nl] = v;
        }
        __syncthreads();

#pragma unroll
        for (int kk = 0; kk < 16; kk++) {
            float a0[4], b0[4];
#pragma unroll
            for (int r = 0; r < 4; r++) a0[r] = As[kk][ty * 4 + r];
#pragma unroll
            for (int c = 0; c < 4; c++) b0[c] = Bs[kk][tx * 4 + c];
#pragma unroll
            for (int r = 0; r < 4; r++)
#pragma unroll
                for (int c = 0; c < 4; c++) acc[r][c] += a0[r] * b0[c];
        }
        __syncthreads();
    }

#pragma unroll
    for (int r = 0; r < 4; r++) {
        int m = m0 + ty * 4 + r;
        if (m >= M) continue;
#pragma unroll
        for (int c = 0; c < 4; c++) {
            int n = n0 + tx * 4 + c;
            if (n < N) out[(long)m * N + n] = acc[r][c] + bias[n];
        }
    }
}

// ---------------------------------------------------------------------------
// GRU gate math for one timestep.
// ---------------------------------------------------------------------------
__global__ void gru_gate(const float* __restrict__ gx_l, const float* __restrict__ gh,
                         const float* __restrict__ hprev, float* __restrict__ hout)
{
    int i = blockIdx.x * blockDim.x + threadIdx.x;
    if (i >= Bv * Hv) return;
    int b = i / Hv, j = i % Hv;
    const float* gxr = gx_l + (long)b * G3;
    const float* ghr = gh + (long)b * G3;
    float r = 1.f / (1.f + expf(-(gxr[j] + ghr[j])));
    float z = 1.f / (1.f + expf(-(gxr[Hv + j] + ghr[Hv + j])));
    float n = tanhf(gxr[2 * Hv + j] + r * ghr[2 * Hv + j]);
    hout[i] = (1.f - z) * n + z * hprev[i];
}

// ---------------------------------------------------------------------------
// Post: co-attention (algebraically collapsed), softmax, pool, logits.
// One block per batch row; h (75x300) cached in dynamic SMEM.
// sm_i = Sw*(a_i + beta) + T + (h_i .* wc) . u
//        - Wmy_i*(a_i + b_i + beta + q_i) + Wmy_b
//   a_i = h_i.wa, b_i = h_i.wb, q_i = sum_d wc_d h_id^2,
//   u_d = sum_j Wmy_j h_jd, T = sum_j Wmy_j b_j, Sw = sum_j Wmy_j
// ---------------------------------------------------------------------------
__device__ __forceinline__ float blockReduceSum(float v, volatile float* red)
{
    __syncthreads();
#pragma unroll
    for (int o = 16; o > 0; o >>= 1) v += __shfl_xor_sync(0xffffffffu, v, o);
    int w = threadIdx.x >> 5, ln = threadIdx.x & 31;
    if (ln == 0) red[w] = v;
    __syncthreads();
    if (threadIdx.x < 32) {
        float x = (threadIdx.x < 8) ? red[threadIdx.x] : 0.f;
#pragma unroll
        for (int o = 4; o > 0; o >>= 1) x += __shfl_xor_sync(0xffffffffu, x, o);
        if (threadIdx.x == 0) red[0] = x;
    }
    __syncthreads();
    return red[0];
}

__device__ __forceinline__ float blockReduceMax(float v, volatile float* red)
{
    __syncthreads();
#pragma unroll
    for (int o = 16; o > 0; o >>= 1) v = fmaxf(v, __shfl_xor_sync(0xffffffffu, v, o));
    int w = threadIdx.x >> 5, ln = threadIdx.x & 31;
    if (ln == 0) red[w] = v;
    __syncthreads();
    if (threadIdx.x < 32) {
        float x = (threadIdx.x < 8) ? red[threadIdx.x] : -3.4e38f;
#pragma unroll
        for (int o = 4; o > 0; o >>= 1) x = fmaxf(x, __shfl_xor_sync(0xffffffffu, x, o));
        if (threadIdx.x == 0) red[0] = x;
    }
    __syncthreads();
    return red[0];
}

__global__ void post_kernel(const float* __restrict__ Hall,
                            const float* __restrict__ wCo_w, const float* __restrict__ wCo_b,
                            const float* __restrict__ Wmy_w, const float* __restrict__ Wmy_b,
                            const float* __restrict__ logits_w, const float* __restrict__ logits_b,
                            float* __restrict__ out)
{
    extern __shared__ float smem[];
    float* h_s    = smem;                  // 22500
    float* wa     = h_s + Lv * Hv;         // 300
    float* wb_    = wa + Hv;               // 300
    float* wc     = wb_ + Hv;              // 300
    float* wmy    = wc + Hv;               // 80
    float* aa     = wmy + 80;              // 80
    float* bb     = aa + 80;               // 80
    float* qq     = bb + 80;               // 80
    float* pp     = qq + 80;               // 80
    float* smarr  = pp + 80;               // 80
    float* attn   = smarr + 80;            // 80
    float* u      = attn + 80;             // 300
    float* pooled = u + Hv;                // 300
    __shared__ float red[32];

    int b = blockIdx.x;
    int tid = threadIdx.x;
    int w = tid >> 5, ln = tid & 31;

    // load h (time-major global -> (i,d) smem), coalesced over d
    for (int t = tid; t < Lv * Hv; t += 256) {
        int i = t / Hv, d = t - i * Hv;
        h_s[t] = Hall[(long)i * Bv * Hv + (long)b * Hv + d];
    }
    for (int t = tid; t < Hv; t += 256) {
        wa[t]  = wCo_w[t];
        wb_[t] = wCo_w[Hv + t];
        wc[t]  = wCo_w[2 * Hv + t];
    }
    if (tid < Lv) wmy[tid] = Wmy_w[tid];
    __syncthreads();

    // pass 1: per-i dots a_i, b_i, q_i (warp per i)
    for (int i = w; i < Lv; i += 8) {
        float sa = 0.f, sb = 0.f, sq = 0.f;
        for (int d = ln; d < Hv; d += 32) {
            float hv = h_s[i * Hv + d];
            sa += hv * wa[d];
            sb += hv * wb_[d];
            sq += hv * hv * wc[d];
        }
#pragma unroll
        for (int o = 16; o > 0; o >>= 1) {
            sa += __shfl_xor_sync(0xffffffffu, sa, o);
            sb += __shfl_xor_sync(0xffffffffu, sb, o);
            sq += __shfl_xor_sync(0xffffffffu, sq, o);
        }
        if (ln == 0) { aa[i] = sa; bb[i] = sb; qq[i] = sq; }
    }
    __syncthreads();

    // u_d = sum_i Wmy_i h_id
    for (int d = tid; d < Hv; d += 256) {
        float s = 0.f;
#pragma unroll 5
        for (int i = 0; i < Lv; i++) s += wmy[i] * h_s[i * Hv + d];
        u[d] = s;
    }

    // Sw, T
    float swv = (tid < Lv) ? wmy[tid] : 0.f;
    float Sw = blockReduceSum(swv, red);
    float tv = (tid < Lv) ? wmy[tid] * bb[tid] : 0.f;
    float T = blockReduceSum(tv, red);
    __syncthreads();

    // pass 2: p_i = (h_i .* wc) . u
    for (int i = w; i < Lv; i += 8) {
        float sp = 0.f;
        for (int d = ln; d < Hv; d += 32) sp += h_s[i * Hv + d] * wc[d] * u[d];
#pragma unroll
        for (int o = 16; o > 0; o >>= 1) sp += __shfl_xor_sync(0xffffffffu, sp, o);
        if (ln == 0) pp[i] = sp;
    }
    __syncthreads();

    float beta = wCo_b[0];
    if (tid < Lv) {
        smarr[tid] = (aa[tid] + beta) * Sw + T + pp[tid]
                   - wmy[tid] * (aa[tid] + bb[tid] + beta + qq[tid]) + Wmy_b[0];
    }
    __syncthreads();

    // softmax over i (75)
    float mv = (tid < Lv) ? smarr[tid] : -3.4e38f;
    float mx = blockReduceMax(mv, red);
    float ev = (tid < Lv) ? expf(smarr[tid] - mx) : 0.f;
    if (tid < Lv) attn[tid] = ev;
    float se = blockReduceSum(ev, red);
    if (tid < Lv) attn[tid] = attn[tid] / se;
    __syncthreads();

    // pooled_d = sum_i attn_i h_id
    for (int d = tid; d < Hv; d += 256) {
        float s = 0.f;
#pragma unroll 5
        for (int i = 0; i < Lv; i++) s += attn[i] * h_s[i * Hv + d];
        pooled[d] = s;
    }
    __syncthreads();

    // logits: warp o computes out[b, o]
    if (w < OUTv) {
        float s = 0.f;
        for (int d = ln; d < Hv; d += 32) s += pooled[d] * logits_w[w * Hv + d];
#pragma unroll
        for (int o = 16; o > 0; o >>= 1) s += __shfl_xor_sync(0xffffffffu, s, o);
        if (ln == 0) out[(long)b * OUTv + w] = s + logits_b[w];
    }
}

// ---------------------------------------------------------------------------
extern "C" void kernel_launch(void* const* d_in, const int* in_sizes, int n_in,
                              void* d_out, int out_size)
{
    const int*   seq      = (const int*)  d_in[0];
    const float* emb      = (const float*)d_in[1];
    const float* W_ih     = (const float*)d_in[2];
    const float* W_hh     = (const float*)d_in[3];
    const float* b_ih     = (const float*)d_in[4];
    const float* b_hh     = (const float*)d_in[5];
    const float* wCo_w    = (const float*)d_in[6];
    const float* wCo_b    = (const float*)d_in[7];
    const float* Wmy_w    = (const float*)d_in[8];
    const float* Wmy_b    = (const float*)d_in[9];
    const float* logits_w = (const float*)d_in[10];
    const float* logits_b = (const float*)d_in[11];
    float* out = (float*)d_out;

    float *gx, *Hall, *gh, *h0;
    cudaGetSymbolAddress((void**)&gx,   d_gx);
    cudaGetSymbolAddress((void**)&Hall, d_Hall);
    cudaGetSymbolAddress((void**)&gh,   d_gh);
    cudaGetSymbolAddress((void**)&h0,   d_h0);

    const int POST_SMEM = (Lv * Hv + 3 * Hv + 7 * 80 + 2 * Hv) * (int)sizeof(float);
    cudaFuncSetAttribute(post_kernel, cudaFuncAttributeMaxDynamicSharedMemorySize, POST_SMEM);

    // 1) gx = emb[seq] @ W_ih^T + b_ih, time-major rows (m = l*B + b)
    {
        dim3 grid((G3 + 63) / 64, (Lv * Bv + 63) / 64);
        gemm_k<<<grid, 256>>>(emb, seq, W_ih, b_ih, gx, Lv * Bv);
    }

    // 2) GRU recurrence: 75 sequential (GEMM + gates)
    for (int l = 0; l < Lv; l++) {
        const float* hprev = (l == 0) ? h0 : (Hall + (long)(l - 1) * Bv * Hv);
        dim3 grid((G3 + 63) / 64, (Bv + 63) / 64);
        gemm_k<<<grid, 256>>>(hprev, nullptr, W_hh, b_hh, gh, Bv);
        gru_gate<<<(Bv * Hv + 255) / 256, 256>>>(gx + (long)l * Bv * G3, gh, hprev,
                                                 Hall + (long)l * Bv * Hv);
    }

    // 3) collapsed co-attention + softmax + pooling + logits
    post_kernel<<<Bv, 256, POST_SMEM>>>(Hall, wCo_w, wCo_b, Wmy_w, Wmy_b,
                                        logits_w, logits_b, out);
}

// round 2
// speedup vs baseline: 1.4400x; 1.4400x over previous
#include <cuda_runtime.h>
#include <math.h>

#define Bv   2048
#define Lv   75
#define Ev   300
#define Hv   300
#define Kv   300
#define G3   900
#define OUTv 5

// ---------------- scratch (device globals; no allocation allowed) ----------
__device__ float d_gx[(long)Lv * Bv * G3];   // (L, B, 900) permuted-col input gates
__device__ float d_Hall[(long)Lv * Bv * Hv]; // (L, B, H) hidden states
__device__ float d_h0[Bv * Hv];              // zero-init, never written => h(-1)=0
__device__ float d_Wp_ih[G3 * Kv];           // W_ih permuted: row 3j+g = orig row g*H+j
__device__ float d_Wp_hh[G3 * Kv];
__device__ float d_bp_ih[G3];
__device__ float d_bp_hh[G3];

// ---------------------------------------------------------------------------
// Permute W rows (g*H+j) -> (3j+g) so gate triples are contiguous columns.
// ---------------------------------------------------------------------------
__global__ void permute_w(const float* __restrict__ W, const float* __restrict__ b,
                          float* __restrict__ Wp, float* __restrict__ bp)
{
    int n = blockIdx.x;           // 0..899 target row = 3j+g
    int j = n / 3, g = n % 3;
    const float* src = W + (long)(g * Hv + j) * Kv;
    float* dst = Wp + (long)n * Kv;
    for (int k = threadIdx.x; k < Kv; k += blockDim.x) dst[k] = src[k];
    if (threadIdx.x == 0) bp[n] = b[g * Hv + j];
}

// ---------------------------------------------------------------------------
// gx GEMM with embedding gather: gx[m][n] = emb[seq] . Wp_ih[n] + bp_ih[n]
// m = l*B + b (time-major), B=2048 so l = m>>11, b = m&2047.
// Tiles: BM=128, BN=96, BK=8; 256 threads; 8x6 per thread.
// ---------------------------------------------------------------------------
__global__ void __launch_bounds__(256)
gx_gemm(const int* __restrict__ seq, const float* __restrict__ emb,
        const float* __restrict__ Wp, const float* __restrict__ bp,
        float* __restrict__ gx)
{
    __shared__ float As[8][128];
    __shared__ float Bs[8][96];

    int tid = threadIdx.x;
    int tx = tid & 15, ty = tid >> 4;
    int m0 = blockIdx.y * 128;
    int n0 = blockIdx.x * 96;

    // A loader assignment: 128 rows x 2 float4
    int la_row = tid >> 1;
    int la_k4  = (tid & 1) * 4;
    int m = m0 + la_row;
    int l  = m >> 11;
    int bb = m & 2047;
    const float* arow = emb + (long)seq[bb * Lv + l] * Ev;

    // B loader assignment: 96 rows x 2 float4 (threads 192..255 idle on loads)
    int lb_n  = tid >> 1;
    int lb_k4 = (tid & 1) * 4;
    bool bload = (lb_n < 96);
    bool bvalid = bload && (n0 + lb_n < G3);
    const float* brow = Wp + (long)(n0 + lb_n) * Kv;

    float acc[8][6];
#pragma unroll
    for (int r = 0; r < 8; r++)
#pragma unroll
        for (int c = 0; c < 6; c++) acc[r][c] = 0.f;

    for (int k0 = 0; k0 < Kv; k0 += 8) {
        {
            int k = k0 + la_k4;
            float4 av = make_float4(0.f, 0.f, 0.f, 0.f);
            if (k + 3 < Kv) av = *(const float4*)(arow + k);
            As[la_k4 + 0][la_row] = av.x;
            As[la_k4 + 1][la_row] = av.y;
            As[la_k4 + 2][la_row] = av.z;
            As[la_k4 + 3][la_row] = av.w;
        }
        if (bload) {
            int k = k0 + lb_k4;
            float4 bv = make_float4(0.f, 0.f, 0.f, 0.f);
            if (bvalid && k + 3 < Kv) bv = *(const float4*)(brow + k);
            Bs[lb_k4 + 0][lb_n] = bv.x;
            Bs[lb_k4 + 1][lb_n] = bv.y;
            Bs[lb_k4 + 2][lb_n] = bv.z;
            Bs[lb_k4 + 3][lb_n] = bv.w;
        }
        __syncthreads();

#pragma unroll
        for (int kk = 0; kk < 8; kk++) {
            float a[8], b[6];
            *(float4*)&a[0] = *(const float4*)&As[kk][ty * 8];
            *(float4*)&a[4] = *(const float4*)&As[kk][ty * 8 + 4];
#pragma unroll
            for (int c = 0; c < 6; c++) b[c] = Bs[kk][tx * 6 + c];
#pragma unroll
            for (int r = 0; r < 8; r++)
#pragma unroll
                for (int c = 0; c < 6; c++) acc[r][c] += a[r] * b[c];
        }
        __syncthreads();
    }

#pragma unroll
    for (int r = 0; r < 8; r++) {
        long mrow = (long)(m0 + ty * 8 + r) * G3;
#pragma unroll
        for (int c = 0; c < 6; c++) {
            int n = n0 + tx * 6 + c;
            if (n < G3) gx[mrow + n] = acc[r][c] + bp[n];
        }
    }
}

// ---------------------------------------------------------------------------
// Fused GRU step: gh = hprev @ Wp_hh^T (+b), gates, h_out. One launch/step.
// Cols tiled 96 = 32 j's x 3 gates; thread's 6 cols = 2 complete (r,z,n) triples.
// grid = (10 j-tiles, 16 m-tiles), 256 threads.
// ---------------------------------------------------------------------------
__global__ void __launch_bounds__(256)
gru_step_k(const float* __restrict__ hprev, const float* __restrict__ Wp,
           const float* __restrict__ bp, const float* __restrict__ gx_l,
           float* __restrict__ hout)
{
    __shared__ float As[8][128];
    __shared__ float Bs[8][96];

    int tid = threadIdx.x;
    int tx = tid & 15, ty = tid >> 4;
    int m0 = blockIdx.y * 128;
    int n0 = blockIdx.x * 96;

    int la_row = tid >> 1;
    int la_k4  = (tid & 1) * 4;
    const float* arow = hprev + (long)(m0 + la_row) * Hv;

    int lb_n  = tid >> 1;
    int lb_k4 = (tid & 1) * 4;
    bool bload = (lb_n < 96);
    bool bvalid = bload && (n0 + lb_n < G3);
    const float* brow = Wp + (long)(n0 + lb_n) * Kv;

    float acc[8][6];
#pragma unroll
    for (int r = 0; r < 8; r++)
#pragma unroll
        for (int c = 0; c < 6; c++) acc[r][c] = 0.f;

    for (int k0 = 0; k0 < Kv; k0 += 8) {
        {
            int k = k0 + la_k4;
            float4 av = make_float4(0.f, 0.f, 0.f, 0.f);
            if (k + 3 < Kv) av = *(const float4*)(arow + k);
            As[la_k4 + 0][la_row] = av.x;
            As[la_k4 + 1][la_row] = av.y;
            As[la_k4 + 2][la_row] = av.z;
            As[la_k4 + 3][la_row] = av.w;
        }
        if (bload) {
            int k = k0 + lb_k4;
            float4 bv = make_float4(0.f, 0.f, 0.f, 0.f);
            if (bvalid && k + 3 < Kv) bv = *(const float4*)(brow + k);
            Bs[lb_k4 + 0][lb_n] = bv.x;
            Bs[lb_k4 + 1][lb_n] = bv.y;
            Bs[lb_k4 + 2][lb_n] = bv.z;
            Bs[lb_k4 + 3][lb_n] = bv.w;
        }
        __syncthreads();

#pragma unroll
        for (int kk = 0; kk < 8; kk++) {
            float a[8], b[6];
            *(float4*)&a[0] = *(const float4*)&As[kk][ty * 8];
            *(float4*)&a[4] = *(const float4*)&As[kk][ty * 8 + 4];
#pragma unroll
            for (int c = 0; c < 6; c++) b[c] = Bs[kk][tx * 6 + c];
#pragma unroll
            for (int r = 0; r < 8; r++)
#pragma unroll
                for (int c = 0; c < 6; c++) acc[r][c] += a[r] * b[c];
        }
        __syncthreads();
    }

    // Gate epilogue: each thread owns 8 rows x 2 complete j triples.
    int jbase = blockIdx.x * 32 + tx * 2;
#pragma unroll
    for (int r = 0; r < 8; r++) {
        int mm = m0 + ty * 8 + r;
        const float* gxr = gx_l + (long)mm * G3;
        const float* hpr = hprev + (long)mm * Hv;
        float* hor = hout + (long)mm * Hv;
#pragma unroll
        for (int p = 0; p < 2; p++) {
            int j = jbase + p;
            if (j < Hv) {
                int nb = 3 * j;   // == n0 + tx*6 + 3p
                float ghr = acc[r][3 * p + 0] + bp[nb + 0];
                float ghz = acc[r][3 * p + 1] + bp[nb + 1];
                float ghn = acc[r][3 * p + 2] + bp[nb + 2];
                float rg = 1.f / (1.f + expf(-(gxr[nb + 0] + ghr)));
                float zg = 1.f / (1.f + expf(-(gxr[nb + 1] + ghz)));
                float ng = tanhf(gxr[nb + 2] + rg * ghn);
                hor[j] = (1.f - zg) * ng + zg * hpr[j];
            }
        }
    }
}

// ---------------------------------------------------------------------------
// Post: collapsed co-attention + softmax + pooling + logits (unchanged math).
// ---------------------------------------------------------------------------
__device__ __forceinline__ float blockReduceSum(float v, volatile float* red)
{
    __syncthreads();
#pragma unroll
    for (int o = 16; o > 0; o >>= 1) v += __shfl_xor_sync(0xffffffffu, v, o);
    int w = threadIdx.x >> 5, ln = threadIdx.x & 31;
    if (ln == 0) red[w] = v;
    __syncthreads();
    if (threadIdx.x < 32) {
        float x = (threadIdx.x < 8) ? red[threadIdx.x] : 0.f;
#pragma unroll
        for (int o = 4; o > 0; o >>= 1) x += __shfl_xor_sync(0xffffffffu, x, o);
        if (threadIdx.x == 0) red[0] = x;
    }
    __syncthreads();
    return red[0];
}

__device__ __forceinline__ float blockReduceMax(float v, volatile float* red)
{
    __syncthreads();
#pragma unroll
    for (int o = 16; o > 0; o >>= 1) v = fmaxf(v, __shfl_xor_sync(0xffffffffu, v, o));
    int w = threadIdx.x >> 5, ln = threadIdx.x & 31;
    if (ln == 0) red[w] = v;
    __syncthreads();
    if (threadIdx.x < 32) {
        float x = (threadIdx.x < 8) ? red[threadIdx.x] : -3.4e38f;
#pragma unroll
        for (int o = 4; o > 0; o >>= 1) x = fmaxf(x, __shfl_xor_sync(0xffffffffu, x, o));
        if (threadIdx.x == 0) red[0] = x;
    }
    __syncthreads();
    return red[0];
}

__global__ void post_kernel(const float* __restrict__ Hall,
                            const float* __restrict__ wCo_w, const float* __restrict__ wCo_b,
                            const float* __restrict__ Wmy_w, const float* __restrict__ Wmy_b,
                            const float* __restrict__ logits_w, const float* __restrict__ logits_b,
                            float* __restrict__ out)
{
    extern __shared__ float smem[];
    float* h_s    = smem;
    float* wa     = h_s + Lv * Hv;
    float* wb_    = wa + Hv;
    float* wc     = wb_ + Hv;
    float* wmy    = wc + Hv;
    float* aa     = wmy + 80;
    float* bb     = aa + 80;
    float* qq     = bb + 80;
    float* pp     = qq + 80;
    float* smarr  = pp + 80;
    float* attn   = smarr + 80;
    float* u      = attn + 80;
    float* pooled = u + Hv;
    __shared__ float red[32];

    int b = blockIdx.x;
    int tid = threadIdx.x;
    int w = tid >> 5, ln = tid & 31;

    for (int t = tid; t < Lv * Hv; t += 256) {
        int i = t / Hv, d = t - i * Hv;
        h_s[t] = Hall[(long)i * Bv * Hv + (long)b * Hv + d];
    }
    for (int t = tid; t < Hv; t += 256) {
        wa[t]  = wCo_w[t];
        wb_[t] = wCo_w[Hv + t];
        wc[t]  = wCo_w[2 * Hv + t];
    }
    if (tid < Lv) wmy[tid] = Wmy_w[tid];
    __syncthreads();

    for (int i = w; i < Lv; i += 8) {
        float sa = 0.f, sb = 0.f, sq = 0.f;
        for (int d = ln; d < Hv; d += 32) {
            float hv = h_s[i * Hv + d];
            sa += hv * wa[d];
            sb += hv * wb_[d];
            sq += hv * hv * wc[d];
        }
#pragma unroll
        for (int o = 16; o > 0; o >>= 1) {
            sa += __shfl_xor_sync(0xffffffffu, sa, o);
            sb += __shfl_xor_sync(0xffffffffu, sb, o);
            sq += __shfl_xor_sync(0xffffffffu, sq, o);
        }
        if (ln == 0) { aa[i] = sa; bb[i] = sb; qq[i] = sq; }
    }
    __syncthreads();

    for (int d = tid; d < Hv; d += 256) {
        float s = 0.f;
#pragma unroll 5
        for (int i = 0; i < Lv; i++) s += wmy[i] * h_s[i * Hv + d];
        u[d] = s;
    }

    float swv = (tid < Lv) ? wmy[tid] : 0.f;
    float Sw = blockReduceSum(swv, red);
    float tv = (tid < Lv) ? wmy[tid] * bb[tid] : 0.f;
    float T = blockReduceSum(tv, red);
    __syncthreads();

    for (int i = w; i < Lv; i += 8) {
        float sp = 0.f;
        for (int d = ln; d < Hv; d += 32) sp += h_s[i * Hv + d] * wc[d] * u[d];
#pragma unroll
        for (int o = 16; o > 0; o >>= 1) sp += __shfl_xor_sync(0xffffffffu, sp, o);
        if (ln == 0) pp[i] = sp;
    }
    __syncthreads();

    float beta = wCo_b[0];
    if (tid < Lv) {
        smarr[tid] = (aa[tid] + beta) * Sw + T + pp[tid]
                   - wmy[tid] * (aa[tid] + bb[tid] + beta + qq[tid]) + Wmy_b[0];
    }
    __syncthreads();

    float mv = (tid < Lv) ? smarr[tid] : -3.4e38f;
    float mx = blockReduceMax(mv, red);
    float ev = (tid < Lv) ? expf(smarr[tid] - mx) : 0.f;
    if (tid < Lv) attn[tid] = ev;
    float se = blockReduceSum(ev, red);
    if (tid < Lv) attn[tid] = attn[tid] / se;
    __syncthreads();

    for (int d = tid; d < Hv; d += 256) {
        float s = 0.f;
#pragma unroll 5
        for (int i = 0; i < Lv; i++) s += attn[i] * h_s[i * Hv + d];
        pooled[d] = s;
    }
    __syncthreads();

    if (w < OUTv) {
        float s = 0.f;
        for (int d = ln; d < Hv; d += 32) s += pooled[d] * logits_w[w * Hv + d];
#pragma unroll
        for (int o = 16; o > 0; o >>= 1) s += __shfl_xor_sync(0xffffffffu, s, o);
        if (ln == 0) out[(long)b * OUTv + w] = s + logits_b[w];
    }
}

// ---------------------------------------------------------------------------
extern "C" void kernel_launch(void* const* d_in, const int* in_sizes, int n_in,
                              void* d_out, int out_size)
{
    const int*   seq      = (const int*)  d_in[0];
    const float* emb      = (const float*)d_in[1];
    const float* W_ih     = (const float*)d_in[2];
    const float* W_hh     = (const float*)d_in[3];
    const float* b_ih     = (const float*)d_in[4];
    const float* b_hh     = (const float*)d_in[5];
    const float* wCo_w    = (const float*)d_in[6];
    const float* wCo_b    = (const float*)d_in[7];
    const float* Wmy_w    = (const float*)d_in[8];
    const float* Wmy_b    = (const float*)d_in[9];
    const float* logits_w = (const float*)d_in[10];
    const float* logits_b = (const float*)d_in[11];
    float* out = (float*)d_out;

    float *gx, *Hall, *h0, *Wp_ih, *Wp_hh, *bp_ih, *bp_hh;
    cudaGetSymbolAddress((void**)&gx,    d_gx);
    cudaGetSymbolAddress((void**)&Hall,  d_Hall);
    cudaGetSymbolAddress((void**)&h0,    d_h0);
    cudaGetSymbolAddress((void**)&Wp_ih, d_Wp_ih);
    cudaGetSymbolAddress((void**)&Wp_hh, d_Wp_hh);
    cudaGetSymbolAddress((void**)&bp_ih, d_bp_ih);
    cudaGetSymbolAddress((void**)&bp_hh, d_bp_hh);

    const int POST_SMEM = (Lv * Hv + 3 * Hv + 7 * 80 + 2 * Hv) * (int)sizeof(float);
    cudaFuncSetAttribute(post_kernel, cudaFuncAttributeMaxDynamicSharedMemorySize, POST_SMEM);

    // 0) permute gate weights to j-interleaved layout
    permute_w<<<G3, 128>>>(W_ih, b_ih, Wp_ih, bp_ih);
    permute_w<<<G3, 128>>>(W_hh, b_hh, Wp_hh, bp_hh);

    // 1) gx = emb[seq] @ Wp_ih^T + bp_ih   (time-major rows m = l*B + b)
    {
        dim3 grid((G3 + 95) / 96, (Lv * Bv) / 128);
        gx_gemm<<<grid, 256>>>(seq, emb, Wp_ih, bp_ih, gx);
    }

    // 2) GRU recurrence: 75 fused (GEMM + gates) launches
    for (int l = 0; l < Lv; l++) {
        const float* hprev = (l == 0) ? h0 : (Hall + (long)(l - 1) * Bv * Hv);
        dim3 grid((G3 + 95) / 96, Bv / 128);
        gru_step_k<<<grid, 256>>>(hprev, Wp_hh, bp_hh,
                                  gx + (long)l * Bv * G3,
                                  Hall + (long)l * Bv * Hv);
    }

    // 3) collapsed co-attention + softmax + pooling + logits
    post_kernel<<<Bv, 256, POST_SMEM>>>(Hall, wCo_w, wCo_b, Wmy_w, Wmy_b,
                                        logits_w, logits_b, out);
}

// round 4
// speedup vs baseline: 2.1532x; 1.4953x over previous
#include <cuda_runtime.h>
#include <cuda_bf16.h>
#include <math.h>
#include <stdint.h>

#define Bv   2048
#define Lv   75
#define Ev   300
#define Hv   300
#define G3   900
#define OUTv 5
#define KP   320                 // K padded to 10 x 32
#define VROWS 50048              // vocab rows padded to 391*128
#define NROWS 960                // gate rows padded to 10*96
#define VOCAB 50000

// ---------------- scratch (device globals; zero-initialized) ---------------
__device__ __nv_bfloat16 d_emb_hi[(size_t)VROWS * KP];
__device__ __nv_bfloat16 d_emb_lo[(size_t)VROWS * KP];
__device__ __nv_bfloat16 d_Wih_hi[NROWS * KP];
__device__ __nv_bfloat16 d_Wih_lo[NROWS * KP];
__device__ __nv_bfloat16 d_Whh_hi[NROWS * KP];
__device__ __nv_bfloat16 d_Whh_lo[NROWS * KP];
__device__ float d_bp_ih[G3];
__device__ float d_bp_hh[G3];
__device__ float d_VG[(size_t)VROWS * G3];                   // vocab gates (b_ih folded)
__device__ __nv_bfloat16 d_Hhi[(size_t)(Lv + 1) * Bv * KP];  // slice 0 = zeros
__device__ __nv_bfloat16 d_Hlo[(size_t)(Lv + 1) * Bv * KP];

// ---------------------------- helpers ---------------------------------------
__device__ __forceinline__ uint32_t smem_u32(const void* p) {
    uint32_t a;
    asm("{ .reg .u64 t; cvta.to.shared.u64 t, %1; cvt.u32.u64 %0, t; }" : "=r"(a) : "l"(p));
    return a;
}
__device__ __forceinline__ void ldsm_x4(uint32_t* r, uint32_t addr) {
    asm volatile("ldmatrix.sync.aligned.m8n8.x4.shared.b16 {%0,%1,%2,%3}, [%4];"
                 : "=r"(r[0]), "=r"(r[1]), "=r"(r[2]), "=r"(r[3]) : "r"(addr));
}
__device__ __forceinline__ void ldsm_x2(uint32_t* r, uint32_t addr) {
    asm volatile("ldmatrix.sync.aligned.m8n8.x2.shared.b16 {%0,%1}, [%2];"
                 : "=r"(r[0]), "=r"(r[1]) : "r"(addr));
}
__device__ __forceinline__ void mma_bf16(float* c, const uint32_t* a, const uint32_t* b) {
    asm volatile(
        "mma.sync.aligned.m16n8k16.row.col.f32.bf16.bf16.f32 "
        "{%0,%1,%2,%3}, {%4,%5,%6,%7}, {%8,%9}, {%0,%1,%2,%3};"
        : "+f"(c[0]), "+f"(c[1]), "+f"(c[2]), "+f"(c[3])
        : "r"(a[0]), "r"(a[1]), "r"(a[2]), "r"(a[3]), "r"(b[0]), "r"(b[1]));
}

// ---------------------------- conversion kernels ---------------------------
__global__ void conv_emb(const float* __restrict__ emb,
                         __nv_bfloat16* __restrict__ hi, __nv_bfloat16* __restrict__ lo)
{
    long i = (long)blockIdx.x * blockDim.x + threadIdx.x;
    if (i >= (long)VOCAB * Ev) return;
    int row = (int)(i / Ev), col = (int)(i - (long)row * Ev);
    float x = emb[i];
    __nv_bfloat16 h = __float2bfloat16(x);
    hi[(size_t)row * KP + col] = h;
    lo[(size_t)row * KP + col] = __float2bfloat16(x - __bfloat162float(h));
}

// permute rows (g*H+j) -> (3j+g), split to bf16 hi/lo, K padded to KP.
__global__ void conv_w(const float* __restrict__ W, const float* __restrict__ b,
                       __nv_bfloat16* __restrict__ hi, __nv_bfloat16* __restrict__ lo,
                       float* __restrict__ bp)
{
    int n = blockIdx.x;            // 0..899
    int j = n / 3, g = n % 3;
    const float* src = W + (size_t)(g * Hv + j) * 300;
    for (int k = threadIdx.x; k < 300; k += blockDim.x) {
        float x = src[k];
        __nv_bfloat16 h = __float2bfloat16(x);
        hi[(size_t)n * KP + k] = h;
        lo[(size_t)n * KP + k] = __float2bfloat16(x - __bfloat162float(h));
    }
    if (threadIdx.x == 0) bp[n] = b[g * Hv + j];
}

// ---------------------------------------------------------------------------
// HMMA GEMM: C(fp32) = (Ahi+Alo) . (Bhi+Blo)^T, 3-term split (drop lo*lo):
//   AhiBhi + AloBhi + AhiBlo, K = 3 x 320, chunks of 32.
// Block 128x96, 8 warps (2m x 4n), warp tile 64x24 (4 x m16, 3 x n8).
// MODE 0: VG epilogue (store fp32 + bias). MODE 1: GRU gate epilogue.
// ---------------------------------------------------------------------------
#define ABF(buf) ((buf) * 5120)            // bf16 units, 128 rows x 40
#define BBF(buf) (10240 + (buf) * 3840)    // 96 rows x 40
#define GH_STRIDE 100
#define SMEM_MMA 51200                     // max(35840 tiles, 128*100*4 epilogue)

template<int MODE>
__global__ void __launch_bounds__(256, 1)
mma_gemm(const __nv_bfloat16* __restrict__ Ahi, const __nv_bfloat16* __restrict__ Alo,
         const __nv_bfloat16* __restrict__ Bhi, const __nv_bfloat16* __restrict__ Blo,
         const float* __restrict__ biasv, float* __restrict__ VGout,
         const int* __restrict__ seq, const float* __restrict__ VGin,
         const float* __restrict__ bph,
         const __nv_bfloat16* __restrict__ Hp_hi, const __nv_bfloat16* __restrict__ Hp_lo,
         __nv_bfloat16* __restrict__ Ho_hi, __nv_bfloat16* __restrict__ Ho_lo,
         int l)
{
    extern __shared__ __align__(16) char smem[];
    __nv_bfloat16* sb16 = (__nv_bfloat16*)smem;
    float* ghs = (float*)smem;
    const uint32_t sbase = smem_u32(smem);

    int tid = threadIdx.x;
    int lane = tid & 31, wid = tid >> 5;
    int wm = wid >> 2, wn = wid & 3;
    int m0 = blockIdx.y * 128;
    int n0 = blockIdx.x * 96;

    // loader coords: each thread 2 A uint4 (rows r, r+64), 1-2 B uint4
    int lr = tid >> 2;                 // 0..63
    int lc = (tid & 3) * 8;            // bf16 col
    // ldmatrix lane offsets
    int a_row = lane & 15, a_k = (lane >> 4) << 3;
    int b_row = lane & 7,  b_k = ((lane >> 3) & 1) << 3;

    float acc[4][3][4];
#pragma unroll
    for (int mi = 0; mi < 4; mi++)
#pragma unroll
        for (int ni = 0; ni < 3; ni++)
#pragma unroll
            for (int q = 0; q < 4; q++) acc[mi][ni][q] = 0.f;

    uint4 pa0, pa1, pb0, pb1;
    // segment tables: 0: hi*hi, 1: lo*hi, 2: hi*lo
#define SEG_A(s) ((s) == 1 ? Alo : Ahi)
#define SEG_B(s) ((s) == 2 ? Blo : Bhi)

    // prefetch chunk 0
    {
        const __nv_bfloat16* Ag = SEG_A(0);
        const __nv_bfloat16* Bg = SEG_B(0);
        pa0 = *(const uint4*)(Ag + (size_t)(m0 + lr) * KP + lc);
        pa1 = *(const uint4*)(Ag + (size_t)(m0 + lr + 64) * KP + lc);
        pb0 = *(const uint4*)(Bg + (size_t)(n0 + lr) * KP + lc);
        if (tid < 128) pb1 = *(const uint4*)(Bg + (size_t)(n0 + 64 + lr) * KP + lc);
    }
    // store chunk 0
    *(uint4*)(sb16 + ABF(0) + lr * 40 + lc) = pa0;
    *(uint4*)(sb16 + ABF(0) + (lr + 64) * 40 + lc) = pa1;
    *(uint4*)(sb16 + BBF(0) + lr * 40 + lc) = pb0;
    if (tid < 128) *(uint4*)(sb16 + BBF(0) + (64 + lr) * 40 + lc) = pb1;
    __syncthreads();

    for (int c = 0; c < 30; c++) {
        if (c < 29) {
            int cn = c + 1;
            int seg = cn / 10;
            int kb = (cn - seg * 10) * 32;
            const __nv_bfloat16* Ag = SEG_A(seg);
            const __nv_bfloat16* Bg = SEG_B(seg);
            pa0 = *(const uint4*)(Ag + (size_t)(m0 + lr) * KP + kb + lc);
            pa1 = *(const uint4*)(Ag + (size_t)(m0 + lr + 64) * KP + kb + lc);
            pb0 = *(const uint4*)(Bg + (size_t)(n0 + lr) * KP + kb + lc);
            if (tid < 128) pb1 = *(const uint4*)(Bg + (size_t)(n0 + 64 + lr) * KP + kb + lc);
        }
        // compute on buf c&1
        {
            int buf = c & 1;
            uint32_t ab = sbase + ABF(buf) * 2;
            uint32_t bb = sbase + BBF(buf) * 2;
#pragma unroll
            for (int kk = 0; kk < 2; kk++) {
                uint32_t afr[4][4], bfr[3][2];
#pragma unroll
                for (int mi = 0; mi < 4; mi++)
                    ldsm_x4(afr[mi], ab + ((wm * 64 + mi * 16 + a_row) * 40 + kk * 16 + a_k) * 2);
#pragma unroll
                for (int ni = 0; ni < 3; ni++)
                    ldsm_x2(bfr[ni], bb + ((wn * 24 + ni * 8 + b_row) * 40 + kk * 16 + b_k) * 2);
#pragma unroll
                for (int mi = 0; mi < 4; mi++)
#pragma unroll
                    for (int ni = 0; ni < 3; ni++)
                        mma_bf16(acc[mi][ni], afr[mi], bfr[ni]);
            }
        }
        if (c < 29) {
            int buf = (c + 1) & 1;
            *(uint4*)(sb16 + ABF(buf) + lr * 40 + lc) = pa0;
            *(uint4*)(sb16 + ABF(buf) + (lr + 64) * 40 + lc) = pa1;
            *(uint4*)(sb16 + BBF(buf) + lr * 40 + lc) = pb0;
            if (tid < 128) *(uint4*)(sb16 + BBF(buf) + (64 + lr) * 40 + lc) = pb1;
        }
        __syncthreads();
    }

    // dump C to smem (padded stride to dodge bank conflicts)
#pragma unroll
    for (int mi = 0; mi < 4; mi++) {
        int mr = wm * 64 + mi * 16 + (lane >> 2);
#pragma unroll
        for (int ni = 0; ni < 3; ni++) {
            int nn = wn * 24 + ni * 8 + (lane & 3) * 2;
            ghs[mr * GH_STRIDE + nn]           = acc[mi][ni][0];
            ghs[mr * GH_STRIDE + nn + 1]       = acc[mi][ni][1];
            ghs[(mr + 8) * GH_STRIDE + nn]     = acc[mi][ni][2];
            ghs[(mr + 8) * GH_STRIDE + nn + 1] = acc[mi][ni][3];
        }
    }
    __syncthreads();

    if (MODE == 0) {
        for (int i = tid; i < 128 * 96; i += 256) {
            int m = i / 96, n = i - m * 96;
            int gn = n0 + n;
            if (gn < G3)
                VGout[(size_t)(m0 + m) * G3 + gn] = ghs[m * GH_STRIDE + n] + biasv[gn];
        }
    } else {
        int j0 = n0 / 3;
        for (int i = tid; i < 128 * 32; i += 256) {
            int ml = i >> 5, p = i & 31;
            int j = j0 + p;
            if (j < Hv) {
                int m = m0 + ml;
                int t = seq[m * Lv + l];
                const float* gxr = VGin + (size_t)t * G3 + n0 + 3 * p;
                int nb = n0 + 3 * p;
                float gh_r = ghs[ml * GH_STRIDE + 3 * p + 0] + bph[nb + 0];
                float gh_z = ghs[ml * GH_STRIDE + 3 * p + 1] + bph[nb + 1];
                float gh_n = ghs[ml * GH_STRIDE + 3 * p + 2] + bph[nb + 2];
                float r = 1.f / (1.f + expf(-(gxr[0] + gh_r)));
                float z = 1.f / (1.f + expf(-(gxr[1] + gh_z)));
                float ng = tanhf(gxr[2] + r * gh_n);
                size_t hidx = (size_t)m * KP + j;
                float hp = __bfloat162float(Hp_hi[hidx]) + __bfloat162float(Hp_lo[hidx]);
                float h = (1.f - z) * ng + z * hp;
                __nv_bfloat16 hh = __float2bfloat16(h);
                Ho_hi[hidx] = hh;
                Ho_lo[hidx] = __float2bfloat16(h - __bfloat162float(hh));
            }
        }
    }
}

// ---------------------------------------------------------------------------
// Post: collapsed co-attention + softmax + pooling + logits.
// ---------------------------------------------------------------------------
__device__ __forceinline__ float blockReduceSum(float v, volatile float* red)
{
    __syncthreads();
#pragma unroll
    for (int o = 16; o > 0; o >>= 1) v += __shfl_xor_sync(0xffffffffu, v, o);
    int w = threadIdx.x >> 5, ln = threadIdx.x & 31;
    if (ln == 0) red[w] = v;
    __syncthreads();
    if (threadIdx.x < 32) {
        float x = (threadIdx.x < 8) ? red[threadIdx.x] : 0.f;
#pragma unroll
        for (int o = 4; o > 0; o >>= 1) x += __shfl_xor_sync(0xffffffffu, x, o);
        if (threadIdx.x == 0) red[0] = x;
    }
    __syncthreads();
    return red[0];
}
__device__ __forceinline__ float blockReduceMax(float v, volatile float* red)
{
    __syncthreads();
#pragma unroll
    for (int o = 16; o > 0; o >>= 1) v = fmaxf(v, __shfl_xor_sync(0xffffffffu, v, o));
    int w = threadIdx.x >> 5, ln = threadIdx.x & 31;
    if (ln == 0) red[w] = v;
    __syncthreads();
    if (threadIdx.x < 32) {
        float x = (threadIdx.x < 8) ? red[threadIdx.x] : -3.4e38f;
#pragma unroll
        for (int o = 4; o > 0; o >>= 1) x = fmaxf(x, __shfl_xor_sync(0xffffffffu, x, o));
        if (threadIdx.x == 0) red[0] = x;
    }
    __syncthreads();
    return red[0];
}

__global__ void post_kernel(const __nv_bfloat16* __restrict__ Hhi,
                            const __nv_bfloat16* __restrict__ Hlo,
                            const float* __restrict__ wCo_w, const float* __restrict__ wCo_b,
                            const float* __restrict__ Wmy_w, const float* __restrict__ Wmy_b,
                            const float* __restrict__ logits_w, const float* __restrict__ logits_b,
                            float* __restrict__ out)
{
    extern __shared__ float fs[];
    float* h_s    = fs;
    float* wa     = h_s + Lv * Hv;
    float* wb_    = wa + Hv;
    float* wc     = wb_ + Hv;
    float* wmy    = wc + Hv;
    float* aa     = wmy + 80;
    float* bb     = aa + 80;
    float* qq     = bb + 80;
    float* pp     = qq + 80;
    float* smarr  = pp + 80;
    float* attn   = smarr + 80;
    float* u      = attn + 80;
    float* pooled = u + Hv;
    __shared__ float red[32];

    int b = blockIdx.x;
    int tid = threadIdx.x;
    int w = tid >> 5, ln = tid & 31;

    for (int t = tid; t < Lv * Hv; t += 256) {
        int i = t / Hv, d = t - i * Hv;
        size_t idx = (size_t)(i + 1) * Bv * KP + (size_t)b * KP + d;
        h_s[t] = __bfloat162float(Hhi[idx]) + __bfloat162float(Hlo[idx]);
    }
    for (int t = tid; t < Hv; t += 256) {
        wa[t]  = wCo_w[t];
        wb_[t] = wCo_w[Hv + t];
        wc[t]  = wCo_w[2 * Hv + t];
    }
    if (tid < Lv) wmy[tid] = Wmy_w[tid];
    __syncthreads();

    for (int i = w; i < Lv; i += 8) {
        float sa = 0.f, sb2 = 0.f, sq = 0.f;
        for (int d = ln; d < Hv; d += 32) {
            float hv = h_s[i * Hv + d];
            sa += hv * wa[d];
            sb2 += hv * wb_[d];
            sq += hv * hv * wc[d];
        }
#pragma unroll
        for (int o = 16; o > 0; o >>= 1) {
            sa += __shfl_xor_sync(0xffffffffu, sa, o);
            sb2 += __shfl_xor_sync(0xffffffffu, sb2, o);
            sq += __shfl_xor_sync(0xffffffffu, sq, o);
        }
        if (ln == 0) { aa[i] = sa; bb[i] = sb2; qq[i] = sq; }
    }
    __syncthreads();

    for (int d = tid; d < Hv; d += 256) {
        float s = 0.f;
#pragma unroll 5
        for (int i = 0; i < Lv; i++) s += wmy[i] * h_s[i * Hv + d];
        u[d] = s;
    }

    float swv = (tid < Lv) ? wmy[tid] : 0.f;
    float Sw = blockReduceSum(swv, red);
    float tv = (tid < Lv) ? wmy[tid] * bb[tid] : 0.f;
    float T = blockReduceSum(tv, red);
    __syncthreads();

    for (int i = w; i < Lv; i += 8) {
        float sp = 0.f;
        for (int d = ln; d < Hv; d += 32) sp += h_s[i * Hv + d] * wc[d] * u[d];
#pragma unroll
        for (int o = 16; o > 0; o >>= 1) sp += __shfl_xor_sync(0xffffffffu, sp, o);
        if (ln == 0) pp[i] = sp;
    }
    __syncthreads();

    float beta = wCo_b[0];
    if (tid < Lv) {
        smarr[tid] = (aa[tid] + beta) * Sw + T + pp[tid]
                   - wmy[tid] * (aa[tid] + bb[tid] + beta + qq[tid]) + Wmy_b[0];
    }
    __syncthreads();

    float mv = (tid < Lv) ? smarr[tid] : -3.4e38f;
    float mx = blockReduceMax(mv, red);
    float ev = (tid < Lv) ? expf(smarr[tid] - mx) : 0.f;
    if (tid < Lv) attn[tid] = ev;
    float se = blockReduceSum(ev, red);
    if (tid < Lv) attn[tid] = attn[tid] / se;
    __syncthreads();

    for (int d = tid; d < Hv; d += 256) {
        float s = 0.f;
#pragma unroll 5
        for (int i = 0; i < Lv; i++) s += attn[i] * h_s[i * Hv + d];
        pooled[d] = s;
    }
    __syncthreads();

    if (w < OUTv) {
        float s = 0.f;
        for (int d = ln; d < Hv; d += 32) s += pooled[d] * logits_w[w * Hv + d];
#pragma unroll
        for (int o = 16; o > 0; o >>= 1) s += __shfl_xor_sync(0xffffffffu, s, o);
        if (ln == 0) out[(size_t)b * OUTv + w] = s + logits_b[w];
    }
}

// ---------------------------------------------------------------------------
extern "C" void kernel_launch(void* const* d_in, const int* in_sizes, int n_in,
                              void* d_out, int out_size)
{
    const int*   seq      = (const int*)  d_in[0];
    const float* emb      = (const float*)d_in[1];
    const float* W_ih     = (const float*)d_in[2];
    const float* W_hh     = (const float*)d_in[3];
    const float* b_ih     = (const float*)d_in[4];
    const float* b_hh     = (const float*)d_in[5];
    const float* wCo_w    = (const float*)d_in[6];
    const float* wCo_b    = (const float*)d_in[7];
    const float* Wmy_w    = (const float*)d_in[8];
    const float* Wmy_b    = (const float*)d_in[9];
    const float* logits_w = (const float*)d_in[10];
    const float* logits_b = (const float*)d_in[11];
    float* out = (float*)d_out;

    __nv_bfloat16 *ehi, *elo, *wih_hi, *wih_lo, *whh_hi, *whh_lo, *Hhi, *Hlo;
    float *bpih, *bphh, *VG;
    cudaGetSymbolAddress((void**)&ehi,    d_emb_hi);
    cudaGetSymbolAddress((void**)&elo,    d_emb_lo);
    cudaGetSymbolAddress((void**)&wih_hi, d_Wih_hi);
    cudaGetSymbolAddress((void**)&wih_lo, d_Wih_lo);
    cudaGetSymbolAddress((void**)&whh_hi, d_Whh_hi);
    cudaGetSymbolAddress((void**)&whh_lo, d_Whh_lo);
    cudaGetSymbolAddress((void**)&bpih,   d_bp_ih);
    cudaGetSymbolAddress((void**)&bphh,   d_bp_hh);
    cudaGetSymbolAddress((void**)&VG,     d_VG);
    cudaGetSymbolAddress((void**)&Hhi,    d_Hhi);
    cudaGetSymbolAddress((void**)&Hlo,    d_Hlo);

    cudaFuncSetAttribute(mma_gemm<0>, cudaFuncAttributeMaxDynamicSharedMemorySize, SMEM_MMA);
    cudaFuncSetAttribute(mma_gemm<1>, cudaFuncAttributeMaxDynamicSharedMemorySize, SMEM_MMA);
    const int POST_SMEM = (Lv * Hv + 3 * Hv + 7 * 80 + 2 * Hv) * (int)sizeof(float);
    cudaFuncSetAttribute(post_kernel, cudaFuncAttributeMaxDynamicSharedMemorySize, POST_SMEM);

    // 0) conversions: emb -> bf16 hi/lo (padded), weights permuted+split
    {
        long n = (long)VOCAB * Ev;
        conv_emb<<<(unsigned)((n + 255) / 256), 256>>>(emb, ehi, elo);
    }
    conv_w<<<G3, 128>>>(W_ih, b_ih, wih_hi, wih_lo, bpih);
    conv_w<<<G3, 128>>>(W_hh, b_hh, whh_hi, whh_lo, bphh);

    // 1) VG = emb @ W_ih^T + b_ih over full vocab (HMMA split-bf16)
    {
        dim3 grid(10, VROWS / 128);
        mma_gemm<0><<<grid, 256, SMEM_MMA>>>(ehi, elo, wih_hi, wih_lo,
                                             bpih, VG,
                                             nullptr, nullptr, nullptr,
                                             nullptr, nullptr, nullptr, nullptr, 0);
    }

    // 2) GRU recurrence: 75 HMMA steps; gx gathered from VG in epilogue
    const size_t slice = (size_t)Bv * KP;
    for (int l = 0; l < Lv; l++) {
        dim3 grid(10, Bv / 128);
        mma_gemm<1><<<grid, 256, SMEM_MMA>>>(Hhi + (size_t)l * slice, Hlo + (size_t)l * slice,
                                             whh_hi, whh_lo,
                                             nullptr, nullptr,
                                             seq, VG, bphh,
                                             Hhi + (size_t)l * slice, Hlo + (size_t)l * slice,
                                             Hhi + (size_t)(l + 1) * slice, Hlo + (size_t)(l + 1) * slice,
                                             l);
    }

    // 3) collapsed co-attention + softmax + pooling + logits
    post_kernel<<<Bv, 256, POST_SMEM>>>(Hhi, Hlo, wCo_w, wCo_b, Wmy_w, Wmy_b,
                                        logits_w, logits_b, out);
}

// round 6
// speedup vs baseline: 3.5640x; 1.6552x over previous
#include <cuda_runtime.h>
#include <cuda_bf16.h>
#include <math.h>
#include <stdint.h>

#define Bv   2048
#define Lv   75
#define Ev   300
#define Hv   300
#define G3   900
#define OUTv 5
#define KP   320                 // K padded to 10 x 32
#define VROWS 50048              // vocab rows padded to 391*128
#define NROWS 960                // gate rows padded to 10*96
#define VOCAB 50000

// ---------------- scratch (device globals; zero-initialized) ---------------
__device__ __nv_bfloat16 d_emb_hi[(size_t)VROWS * KP];
__device__ __nv_bfloat16 d_emb_lo[(size_t)VROWS * KP];
__device__ __nv_bfloat16 d_Wih_hi[NROWS * KP];
__device__ __nv_bfloat16 d_Wih_lo[NROWS * KP];
__device__ __nv_bfloat16 d_Whh_hi[NROWS * KP];
__device__ __nv_bfloat16 d_Whh_lo[NROWS * KP];
__device__ float d_bp_ih[G3];
__device__ float d_bp_hh[G3];
__device__ float d_VG[(size_t)VROWS * G3];                   // vocab gates (b_ih + rz(b_hh) folded)
__device__ __nv_bfloat16 d_Hhi[(size_t)(Lv + 1) * Bv * KP];  // slice 0 = zeros
__device__ __nv_bfloat16 d_Hlo[(size_t)(Lv + 1) * Bv * KP];

// ---------------------------- helpers ---------------------------------------
__device__ __forceinline__ uint32_t smem_u32(const void* p) {
    uint32_t a;
    asm("{ .reg .u64 t; cvta.to.shared.u64 t, %1; cvt.u32.u64 %0, t; }" : "=r"(a) : "l"(p));
    return a;
}
__device__ __forceinline__ void ldsm_x4(uint32_t* r, uint32_t addr) {
    asm volatile("ldmatrix.sync.aligned.m8n8.x4.shared.b16 {%0,%1,%2,%3}, [%4];"
                 : "=r"(r[0]), "=r"(r[1]), "=r"(r[2]), "=r"(r[3]) : "r"(addr));
}
__device__ __forceinline__ void ldsm_x2(uint32_t* r, uint32_t addr) {
    asm volatile("ldmatrix.sync.aligned.m8n8.x2.shared.b16 {%0,%1}, [%2];"
                 : "=r"(r[0]), "=r"(r[1]) : "r"(addr));
}
__device__ __forceinline__ void mma_bf16(float* c, const uint32_t* a, const uint32_t* b) {
    asm volatile(
        "mma.sync.aligned.m16n8k16.row.col.f32.bf16.bf16.f32 "
        "{%0,%1,%2,%3}, {%4,%5,%6,%7}, {%8,%9}, {%0,%1,%2,%3};"
        : "+f"(c[0]), "+f"(c[1]), "+f"(c[2]), "+f"(c[3])
        : "r"(a[0]), "r"(a[1]), "r"(a[2]), "r"(a[3]), "r"(b[0]), "r"(b[1]));
}
__device__ __forceinline__ void cp16(uint32_t dst, const void* src) {
    asm volatile("cp.async.cg.shared.global [%0], [%1], 16;" :: "r"(dst), "l"(src));
}
#define CP_COMMIT() asm volatile("cp.async.commit_group;" ::: "memory")
#define CP_WAIT0()  asm volatile("cp.async.wait_group 0;" ::: "memory")

// ---------------------------- conversion kernels ---------------------------
__global__ void conv_emb(const float* __restrict__ emb,
                         __nv_bfloat16* __restrict__ hi, __nv_bfloat16* __restrict__ lo)
{
    long i = (long)blockIdx.x * blockDim.x + threadIdx.x;
    if (i >= (long)VOCAB * Ev) return;
    int row = (int)(i / Ev), col = (int)(i - (long)row * Ev);
    float x = emb[i];
    __nv_bfloat16 h = __float2bfloat16(x);
    hi[(size_t)row * KP + col] = h;
    lo[(size_t)row * KP + col] = __float2bfloat16(x - __bfloat162float(h));
}

// permute rows (g*H+j) -> (3j+g), split to bf16 hi/lo, K padded to KP.
__global__ void conv_w(const float* __restrict__ W, const float* __restrict__ b,
                       __nv_bfloat16* __restrict__ hi, __nv_bfloat16* __restrict__ lo,
                       float* __restrict__ bp)
{
    int n = blockIdx.x;            // 0..899
    int j = n / 3, g = n % 3;
    const float* src = W + (size_t)(g * Hv + j) * 300;
    for (int k = threadIdx.x; k < 300; k += blockDim.x) {
        float x = src[k];
        __nv_bfloat16 h = __float2bfloat16(x);
        hi[(size_t)n * KP + k] = h;
        lo[(size_t)n * KP + k] = __float2bfloat16(x - __bfloat162float(h));
    }
    if (threadIdx.x == 0) bp[n] = b[g * Hv + j];
}

// ---------------------------------------------------------------------------
// VG GEMM: VG = emb @ W_ih^T + b_ih + (b_hh for r,z gates ONLY).
// The n-gate b_hh component stays out: it is multiplied by r in the GRU cell.
// Block 128x96, 8 warps (2m x 4n), warp tile 64x24.
// ---------------------------------------------------------------------------
#define ABF(buf) ((buf) * 5120)            // bf16 units, 128 rows x 40
#define BBF(buf) (10240 + (buf) * 3840)    // 96 rows x 40
#define GH_STRIDE 100
#define SMEM_VG 51200

__global__ void __launch_bounds__(256)
vg_gemm(const __nv_bfloat16* __restrict__ Ahi, const __nv_bfloat16* __restrict__ Alo,
        const __nv_bfloat16* __restrict__ Bhi, const __nv_bfloat16* __restrict__ Blo,
        const float* __restrict__ bias1, const float* __restrict__ bias2,
        float* __restrict__ VGout)
{
    extern __shared__ __align__(16) char smem[];
    __nv_bfloat16* sb16 = (__nv_bfloat16*)smem;
    float* ghs = (float*)smem;
    const uint32_t sbase = smem_u32(smem);

    int tid = threadIdx.x;
    int lane = tid & 31, wid = tid >> 5;
    int wm = wid >> 2, wn = wid & 3;
    int m0 = blockIdx.y * 128;
    int n0 = blockIdx.x * 96;

    int lr = tid >> 2;
    int lc = (tid & 3) * 8;
    int a_row = lane & 15, a_k = (lane >> 4) << 3;
    int b_row = lane & 7,  b_k = ((lane >> 3) & 1) << 3;

    float acc[4][3][4];
#pragma unroll
    for (int mi = 0; mi < 4; mi++)
#pragma unroll
        for (int ni = 0; ni < 3; ni++)
#pragma unroll
            for (int q = 0; q < 4; q++) acc[mi][ni][q] = 0.f;

    uint4 pa0, pa1, pb0, pb1;
#define SEG_A(s) ((s) == 1 ? Alo : Ahi)
#define SEG_B(s) ((s) == 2 ? Blo : Bhi)

    {
        const __nv_bfloat16* Ag = SEG_A(0);
        const __nv_bfloat16* Bg = SEG_B(0);
        pa0 = *(const uint4*)(Ag + (size_t)(m0 + lr) * KP + lc);
        pa1 = *(const uint4*)(Ag + (size_t)(m0 + lr + 64) * KP + lc);
        pb0 = *(const uint4*)(Bg + (size_t)(n0 + lr) * KP + lc);
        if (tid < 128) pb1 = *(const uint4*)(Bg + (size_t)(n0 + 64 + lr) * KP + lc);
    }
    *(uint4*)(sb16 + ABF(0) + lr * 40 + lc) = pa0;
    *(uint4*)(sb16 + ABF(0) + (lr + 64) * 40 + lc) = pa1;
    *(uint4*)(sb16 + BBF(0) + lr * 40 + lc) = pb0;
    if (tid < 128) *(uint4*)(sb16 + BBF(0) + (64 + lr) * 40 + lc) = pb1;
    __syncthreads();

    for (int c = 0; c < 30; c++) {
        if (c < 29) {
            int cn = c + 1;
            int seg = cn / 10;
            int kb = (cn - seg * 10) * 32;
            const __nv_bfloat16* Ag = SEG_A(seg);
            const __nv_bfloat16* Bg = SEG_B(seg);
            pa0 = *(const uint4*)(Ag + (size_t)(m0 + lr) * KP + kb + lc);
            pa1 = *(const uint4*)(Ag + (size_t)(m0 + lr + 64) * KP + kb + lc);
            pb0 = *(const uint4*)(Bg + (size_t)(n0 + lr) * KP + kb + lc);
            if (tid < 128) pb1 = *(const uint4*)(Bg + (size_t)(n0 + 64 + lr) * KP + kb + lc);
        }
        {
            int buf = c & 1;
            uint32_t ab = sbase + ABF(buf) * 2;
            uint32_t bb = sbase + BBF(buf) * 2;
#pragma unroll
            for (int kk = 0; kk < 2; kk++) {
                uint32_t afr[4][4], bfr[3][2];
#pragma unroll
                for (int mi = 0; mi < 4; mi++)
                    ldsm_x4(afr[mi], ab + ((wm * 64 + mi * 16 + a_row) * 40 + kk * 16 + a_k) * 2);
#pragma unroll
                for (int ni = 0; ni < 3; ni++)
                    ldsm_x2(bfr[ni], bb + ((wn * 24 + ni * 8 + b_row) * 40 + kk * 16 + b_k) * 2);
#pragma unroll
                for (int mi = 0; mi < 4; mi++)
#pragma unroll
                    for (int ni = 0; ni < 3; ni++)
                        mma_bf16(acc[mi][ni], afr[mi], bfr[ni]);
            }
        }
        if (c < 29) {
            int buf = (c + 1) & 1;
            *(uint4*)(sb16 + ABF(buf) + lr * 40 + lc) = pa0;
            *(uint4*)(sb16 + ABF(buf) + (lr + 64) * 40 + lc) = pa1;
            *(uint4*)(sb16 + BBF(buf) + lr * 40 + lc) = pb0;
            if (tid < 128) *(uint4*)(sb16 + BBF(buf) + (64 + lr) * 40 + lc) = pb1;
        }
        __syncthreads();
    }

#pragma unroll
    for (int mi = 0; mi < 4; mi++) {
        int mr = wm * 64 + mi * 16 + (lane >> 2);
#pragma unroll
        for (int ni = 0; ni < 3; ni++) {
            int nn = wn * 24 + ni * 8 + (lane & 3) * 2;
            ghs[mr * GH_STRIDE + nn]           = acc[mi][ni][0];
            ghs[mr * GH_STRIDE + nn + 1]       = acc[mi][ni][1];
            ghs[(mr + 8) * GH_STRIDE + nn]     = acc[mi][ni][2];
            ghs[(mr + 8) * GH_STRIDE + nn + 1] = acc[mi][ni][3];
        }
    }
    __syncthreads();

    for (int i = tid; i < 128 * 96; i += 256) {
        int m = i / 96, n = i - m * 96;
        int gn = n0 + n;
        if (gn < G3) {
            // gate index g = gn % 3; fold b_hh only for r (0) and z (1) gates.
            float b2 = (gn % 3 != 2) ? bias2[gn] : 0.f;
            VGout[(size_t)(m0 + m) * G3 + gn] = ghs[m * GH_STRIDE + n] + bias1[gn] + b2;
        }
    }
}

// ---------------------------------------------------------------------------
// GRU step: gh = h_prev @ Whh^T (3-term bf16 split) fused with gate epilogue.
// Block 64x96, 8 warps (2m x 4n), warp tile 32x24. grid (10, 32) = 320 blocks.
// gx slice (VG gather) + h_prev slice prefetched via cp.async at kernel start.
// n-gate b_hh added to gh_n in the epilogue (inside the r* product).
// ---------------------------------------------------------------------------
#define SAB(buf) ((buf) * 2560)            // bf16 units, 64 x 40
#define SBB(buf) (5120 + (buf) * 3840)     // 96 x 40
#define GX_B  25600
#define HPH_B 50176
#define HPL_B 54272
#define BHN_B 58368                        // 32 floats: b_hh n-gate for this j tile
#define SMEM_STEP 58496

__global__ void __launch_bounds__(256)
gru_step(const __nv_bfloat16* __restrict__ Hp_hi, const __nv_bfloat16* __restrict__ Hp_lo,
         const __nv_bfloat16* __restrict__ Bhi, const __nv_bfloat16* __restrict__ Blo,
         const int* __restrict__ seq, const float* __restrict__ VGin,
         const float* __restrict__ bph,
         __nv_bfloat16* __restrict__ Ho_hi, __nv_bfloat16* __restrict__ Ho_lo,
         int l)
{
    extern __shared__ __align__(16) char smem[];
    __nv_bfloat16* sb16 = (__nv_bfloat16*)smem;
    float* cs  = (float*)smem;
    float* gxs = (float*)(smem + GX_B);
    __nv_bfloat16* hph = (__nv_bfloat16*)(smem + HPH_B);
    __nv_bfloat16* hpl = (__nv_bfloat16*)(smem + HPL_B);
    float* bhn = (float*)(smem + BHN_B);
    const uint32_t sbase = smem_u32(smem);

    int tid = threadIdx.x;
    int lane = tid & 31, wid = tid >> 5;
    int wm = wid >> 2, wn = wid & 3;
    int m0 = blockIdx.y * 64;
    int n0 = blockIdx.x * 96;
    int j0 = blockIdx.x * 32;

    // ---- prefetch epilogue data (gx gather + h_prev) via cp.async ----
#pragma unroll
    for (int c = 0; c < 6; c++) {
        int idx = tid + c * 256;           // 0..1535
        int row = idx / 24, off = (idx % 24) * 4;
        int t = seq[(m0 + row) * Lv + l];
        cp16(sbase + GX_B + (uint32_t)(row * 96 + off) * 4,
             VGin + (size_t)t * G3 + n0 + off);
    }
    {
        int row = tid >> 2, off = (tid & 3) * 8;
        cp16(sbase + HPH_B + (uint32_t)(row * 32 + off) * 2,
             Hp_hi + (size_t)(m0 + row) * KP + j0 + off);
        cp16(sbase + HPL_B + (uint32_t)(row * 32 + off) * 2,
             Hp_lo + (size_t)(m0 + row) * KP + j0 + off);
    }
    if (tid < 32) bhn[tid] = bph[n0 + 3 * tid + 2];   // b_hh n-gate for j0+tid
    CP_COMMIT();

    // ---- GEMM ----
    int lr = tid >> 2;
    int lc = (tid & 3) * 8;
    int a_row = lane & 15, a_k = (lane >> 4) << 3;
    int b_row = lane & 7,  b_k = ((lane >> 3) & 1) << 3;

    float acc[2][3][4];
#pragma unroll
    for (int mi = 0; mi < 2; mi++)
#pragma unroll
        for (int ni = 0; ni < 3; ni++)
#pragma unroll
            for (int q = 0; q < 4; q++) acc[mi][ni][q] = 0.f;

    uint4 pa, pb0, pb1;
#define SEG_AH(s) ((s) == 1 ? Hp_lo : Hp_hi)
#define SEG_BH(s) ((s) == 2 ? Blo : Bhi)
    {
        const __nv_bfloat16* Ag = SEG_AH(0);
        const __nv_bfloat16* Bg = SEG_BH(0);
        pa  = *(const uint4*)(Ag + (size_t)(m0 + lr) * KP + lc);
        pb0 = *(const uint4*)(Bg + (size_t)(n0 + lr) * KP + lc);
        if (tid < 128) pb1 = *(const uint4*)(Bg + (size_t)(n0 + 64 + lr) * KP + lc);
    }
    *(uint4*)(sb16 + SAB(0) + lr * 40 + lc) = pa;
    *(uint4*)(sb16 + SBB(0) + lr * 40 + lc) = pb0;
    if (tid < 128) *(uint4*)(sb16 + SBB(0) + (64 + lr) * 40 + lc) = pb1;
    __syncthreads();

    for (int c = 0; c < 30; c++) {
        if (c < 29) {
            int cn = c + 1;
            int seg = cn / 10;
            int kb = (cn - seg * 10) * 32;
            const __nv_bfloat16* Ag = SEG_AH(seg);
            const __nv_bfloat16* Bg = SEG_BH(seg);
            pa  = *(const uint4*)(Ag + (size_t)(m0 + lr) * KP + kb + lc);
            pb0 = *(const uint4*)(Bg + (size_t)(n0 + lr) * KP + kb + lc);
            if (tid < 128) pb1 = *(const uint4*)(Bg + (size_t)(n0 + 64 + lr) * KP + kb + lc);
        }
        {
            int buf = c & 1;
            uint32_t ab = sbase + SAB(buf) * 2;
            uint32_t bb = sbase + SBB(buf) * 2;
#pragma unroll
            for (int kk = 0; kk < 2; kk++) {
                uint32_t afr[2][4], bfr[3][2];
#pragma unroll
                for (int mi = 0; mi < 2; mi++)
                    ldsm_x4(afr[mi], ab + ((wm * 32 + mi * 16 + a_row) * 40 + kk * 16 + a_k) * 2);
#pragma unroll
                for (int ni = 0; ni < 3; ni++)
                    ldsm_x2(bfr[ni], bb + ((wn * 24 + ni * 8 + b_row) * 40 + kk * 16 + b_k) * 2);
#pragma unroll
                for (int mi = 0; mi < 2; mi++)
#pragma unroll
                    for (int ni = 0; ni < 3; ni++)
                        mma_bf16(acc[mi][ni], afr[mi], bfr[ni]);
            }
        }
        if (c < 29) {
            int buf = (c + 1) & 1;
            *(uint4*)(sb16 + SAB(buf) + lr * 40 + lc) = pa;
            *(uint4*)(sb16 + SBB(buf) + lr * 40 + lc) = pb0;
            if (tid < 128) *(uint4*)(sb16 + SBB(buf) + (64 + lr) * 40 + lc) = pb1;
        }
        __syncthreads();
    }

    // ---- dump C to smem (aliases tile buffers; K loop fully synced) ----
#pragma unroll
    for (int mi = 0; mi < 2; mi++) {
        int mr = wm * 32 + mi * 16 + (lane >> 2);
#pragma unroll
        for (int ni = 0; ni < 3; ni++) {
            int nn = wn * 24 + ni * 8 + (lane & 3) * 2;
            cs[mr * GH_STRIDE + nn]           = acc[mi][ni][0];
            cs[mr * GH_STRIDE + nn + 1]       = acc[mi][ni][1];
            cs[(mr + 8) * GH_STRIDE + nn]     = acc[mi][ni][2];
            cs[(mr + 8) * GH_STRIDE + nn + 1] = acc[mi][ni][3];
        }
    }
    CP_WAIT0();
    __syncthreads();

    // ---- gate epilogue ----
    for (int i = tid; i < 64 * 32; i += 256) {
        int ml = i >> 5, p = i & 31;
        int j = j0 + p;
        if (j < Hv) {
            int m = m0 + ml;
            float gh_r = cs[ml * GH_STRIDE + 3 * p + 0];
            float gh_z = cs[ml * GH_STRIDE + 3 * p + 1];
            float gh_n = cs[ml * GH_STRIDE + 3 * p + 2] + bhn[p];  // b_hh_n inside r*(.)
            float gx_r = gxs[ml * 96 + 3 * p + 0];
            float gx_z = gxs[ml * 96 + 3 * p + 1];
            float gx_n = gxs[ml * 96 + 3 * p + 2];
            float r = 1.f / (1.f + expf(-(gx_r + gh_r)));
            float z = 1.f / (1.f + expf(-(gx_z + gh_z)));
            float ng = tanhf(gx_n + r * gh_n);
            float hp = __bfloat162float(hph[ml * 32 + p]) + __bfloat162float(hpl[ml * 32 + p]);
            float h = (1.f - z) * ng + z * hp;
            size_t hidx = (size_t)m * KP + j;
            __nv_bfloat16 hh = __float2bfloat16(h);
            Ho_hi[hidx] = hh;
            Ho_lo[hidx] = __float2bfloat16(h - __bfloat162float(hh));
        }
    }
}

// ---------------------------------------------------------------------------
// Post: collapsed co-attention + softmax + pooling + logits.
// ---------------------------------------------------------------------------
__device__ __forceinline__ float blockReduceSum(float v, volatile float* red)
{
    __syncthreads();
#pragma unroll
    for (int o = 16; o > 0; o >>= 1) v += __shfl_xor_sync(0xffffffffu, v, o);
    int w = threadIdx.x >> 5, ln = threadIdx.x & 31;
    if (ln == 0) red[w] = v;
    __syncthreads();
    if (threadIdx.x < 32) {
        float x = (threadIdx.x < 8) ? red[threadIdx.x] : 0.f;
#pragma unroll
        for (int o = 4; o > 0; o >>= 1) x += __shfl_xor_sync(0xffffffffu, x, o);
        if (threadIdx.x == 0) red[0] = x;
    }
    __syncthreads();
    return red[0];
}
__device__ __forceinline__ float blockReduceMax(float v, volatile float* red)
{
    __syncthreads();
#pragma unroll
    for (int o = 16; o > 0; o >>= 1) v = fmaxf(v, __shfl_xor_sync(0xffffffffu, v, o));
    int w = threadIdx.x >> 5, ln = threadIdx.x & 31;
    if (ln == 0) red[w] = v;
    __syncthreads();
    if (threadIdx.x < 32) {
        float x = (threadIdx.x < 8) ? red[threadIdx.x] : -3.4e38f;
#pragma unroll
        for (int o = 4; o > 0; o >>= 1) x = fmaxf(x, __shfl_xor_sync(0xffffffffu, x, o));
        if (threadIdx.x == 0) red[0] = x;
    }
    __syncthreads();
    return red[0];
}

__global__ void post_kernel(const __nv_bfloat16* __restrict__ Hhi,
                            const __nv_bfloat16* __restrict__ Hlo,
                            const float* __restrict__ wCo_w, const float* __restrict__ wCo_b,
                            const float* __restrict__ Wmy_w, const float* __restrict__ Wmy_b,
                            const float* __restrict__ logits_w, const float* __restrict__ logits_b,
                            float* __restrict__ out)
{
    extern __shared__ float fs[];
    float* h_s    = fs;
    float* wa     = h_s + Lv * Hv;
    float* wb_    = wa + Hv;
    float* wc     = wb_ + Hv;
    float* wmy    = wc + Hv;
    float* aa     = wmy + 80;
    float* bb     = aa + 80;
    float* qq     = bb + 80;
    float* pp     = qq + 80;
    float* smarr  = pp + 80;
    float* attn   = smarr + 80;
    float* u      = attn + 80;
    float* pooled = u + Hv;
    __shared__ float red[32];

    int b = blockIdx.x;
    int tid = threadIdx.x;
    int w = tid >> 5, ln = tid & 31;

    for (int t = tid; t < Lv * Hv; t += 256) {
        int i = t / Hv, d = t - i * Hv;
        size_t idx = (size_t)(i + 1) * Bv * KP + (size_t)b * KP + d;
        h_s[t] = __bfloat162float(Hhi[idx]) + __bfloat162float(Hlo[idx]);
    }
    for (int t = tid; t < Hv; t += 256) {
        wa[t]  = wCo_w[t];
        wb_[t] = wCo_w[Hv + t];
        wc[t]  = wCo_w[2 * Hv + t];
    }
    if (tid < Lv) wmy[tid] = Wmy_w[tid];
    __syncthreads();

    for (int i = w; i < Lv; i += 8) {
        float sa = 0.f, sb2 = 0.f, sq = 0.f;
        for (int d = ln; d < Hv; d += 32) {
            float hv = h_s[i * Hv + d];
            sa += hv * wa[d];
            sb2 += hv * wb_[d];
            sq += hv * hv * wc[d];
        }
#pragma unroll
        for (int o = 16; o > 0; o >>= 1) {
            sa += __shfl_xor_sync(0xffffffffu, sa, o);
            sb2 += __shfl_xor_sync(0xffffffffu, sb2, o);
            sq += __shfl_xor_sync(0xffffffffu, sq, o);
        }
        if (ln == 0) { aa[i] = sa; bb[i] = sb2; qq[i] = sq; }
    }
    __syncthreads();

    for (int d = tid; d < Hv; d += 256) {
        float s = 0.f;
#pragma unroll 5
        for (int i = 0; i < Lv; i++) s += wmy[i] * h_s[i * Hv + d];
        u[d] = s;
    }

    float swv = (tid < Lv) ? wmy[tid] : 0.f;
    float Sw = blockReduceSum(swv, red);
    float tv = (tid < Lv) ? wmy[tid] * bb[tid] : 0.f;
    float T = blockReduceSum(tv, red);
    __syncthreads();

    for (int i = w; i < Lv; i += 8) {
        float sp = 0.f;
        for (int d = ln; d < Hv; d += 32) sp += h_s[i * Hv + d] * wc[d] * u[d];
#pragma unroll
        for (int o = 16; o > 0; o >>= 1) sp += __shfl_xor_sync(0xffffffffu, sp, o);
        if (ln == 0) pp[i] = sp;
    }
    __syncthreads();

    float beta = wCo_b[0];
    if (tid < Lv) {
        smarr[tid] = (aa[tid] + beta) * Sw + T + pp[tid]
                   - wmy[tid] * (aa[tid] + bb[tid] + beta + qq[tid]) + Wmy_b[0];
    }
    __syncthreads();

    float mv = (tid < Lv) ? smarr[tid] : -3.4e38f;
    float mx = blockReduceMax(mv, red);
    float ev = (tid < Lv) ? expf(smarr[tid] - mx) : 0.f;
    if (tid < Lv) attn[tid] = ev;
    float se = blockReduceSum(ev, red);
    if (tid < Lv) attn[tid] = attn[tid] / se;
    __syncthreads();

    for (int d = tid; d < Hv; d += 256) {
        float s = 0.f;
#pragma unroll 5
        for (int i = 0; i < Lv; i++) s += attn[i] * h_s[i * Hv + d];
        pooled[d] = s;
    }
    __syncthreads();

    if (w < OUTv) {
        float s = 0.f;
        for (int d = ln; d < Hv; d += 32) s += pooled[d] * logits_w[w * Hv + d];
#pragma unroll
        for (int o = 16; o > 0; o >>= 1) s += __shfl_xor_sync(0xffffffffu, s, o);
        if (ln == 0) out[(size_t)b * OUTv + w] = s + logits_b[w];
    }
}

// ---------------------------------------------------------------------------
extern "C" void kernel_launch(void* const* d_in, const int* in_sizes, int n_in,
                              void* d_out, int out_size)
{
    const int*   seq      = (const int*)  d_in[0];
    const float* emb      = (const float*)d_in[1];
    const float* W_ih     = (const float*)d_in[2];
    const float* W_hh     = (const float*)d_in[3];
    const float* b_ih     = (const float*)d_in[4];
    const float* b_hh     = (const float*)d_in[5];
    const float* wCo_w    = (const float*)d_in[6];
    const float* wCo_b    = (const float*)d_in[7];
    const float* Wmy_w    = (const float*)d_in[8];
    const float* Wmy_b    = (const float*)d_in[9];
    const float* logits_w = (const float*)d_in[10];
    const float* logits_b = (const float*)d_in[11];
    float* out = (float*)d_out;

    __nv_bfloat16 *ehi, *elo, *wih_hi, *wih_lo, *whh_hi, *whh_lo, *Hhi, *Hlo;
    float *bpih, *bphh, *VG;
    cudaGetSymbolAddress((void**)&ehi,    d_emb_hi);
    cudaGetSymbolAddress((void**)&elo,    d_emb_lo);
    cudaGetSymbolAddress((void**)&wih_hi, d_Wih_hi);
    cudaGetSymbolAddress((void**)&wih_lo, d_Wih_lo);
    cudaGetSymbolAddress((void**)&whh_hi, d_Whh_hi);
    cudaGetSymbolAddress((void**)&whh_lo, d_Whh_lo);
    cudaGetSymbolAddress((void**)&bpih,   d_bp_ih);
    cudaGetSymbolAddress((void**)&bphh,   d_bp_hh);
    cudaGetSymbolAddress((void**)&VG,     d_VG);
    cudaGetSymbolAddress((void**)&Hhi,    d_Hhi);
    cudaGetSymbolAddress((void**)&Hlo,    d_Hlo);

    cudaFuncSetAttribute(vg_gemm, cudaFuncAttributeMaxDynamicSharedMemorySize, SMEM_VG);
    cudaFuncSetAttribute(gru_step, cudaFuncAttributeMaxDynamicSharedMemorySize, SMEM_STEP);
    const int POST_SMEM = (Lv * Hv + 3 * Hv + 7 * 80 + 2 * Hv) * (int)sizeof(float);
    cudaFuncSetAttribute(post_kernel, cudaFuncAttributeMaxDynamicSharedMemorySize, POST_SMEM);

    // 0) conversions: emb -> bf16 hi/lo (padded), weights permuted+split
    {
        long n = (long)VOCAB * Ev;
        conv_emb<<<(unsigned)((n + 255) / 256), 256>>>(emb, ehi, elo);
    }
    conv_w<<<G3, 128>>>(W_ih, b_ih, wih_hi, wih_lo, bpih);
    conv_w<<<G3, 128>>>(W_hh, b_hh, whh_hi, whh_lo, bphh);

    // 1) VG = emb @ W_ih^T + b_ih + rz(b_hh) over full vocab
    {
        dim3 grid(10, VROWS / 128);
        vg_gemm<<<grid, 256, SMEM_VG>>>(ehi, elo, wih_hi, wih_lo, bpih, bphh, VG);
    }

    // 2) GRU recurrence: 75 fused steps, gather prefetched via cp.async
    const size_t slice = (size_t)Bv * KP;
    for (int l = 0; l < Lv; l++) {
        dim3 grid(10, Bv / 64);
        gru_step<<<grid, 256, SMEM_STEP>>>(Hhi + (size_t)l * slice, Hlo + (size_t)l * slice,
                                           whh_hi, whh_lo,
                                           seq, VG, bphh,
                                           Hhi + (size_t)(l + 1) * slice, Hlo + (size_t)(l + 1) * slice,
                                           l);
    }

    // 3) collapsed co-attention + softmax + pooling + logits
    post_kernel<<<Bv, 256, POST_SMEM>>>(Hhi, Hlo, wCo_w, wCo_b, Wmy_w, Wmy_b,
                                        logits_w, logits_b, out);
}

// round 7
// speedup vs baseline: 4.9143x; 1.3789x over previous
#include <cuda_runtime.h>
#include <cuda_bf16.h>
#include <math.h>
#include <stdint.h>

#define Bv   2048
#define Lv   75
#define Ev   300
#define Hv   300
#define G3   900
#define OUTv 5
#define KP   320                 // K padded to 10 x 32
#define VROWS 50048              // vocab rows padded to 391*128
#define NROWS 960                // gate rows padded to 10*96
#define VOCAB 50000

// ---------------- scratch (device globals; zero-initialized) ---------------
__device__ __nv_bfloat16 d_emb_hi[(size_t)VROWS * KP];
__device__ __nv_bfloat16 d_emb_lo[(size_t)VROWS * KP];
__device__ __nv_bfloat16 d_Wih_hi[NROWS * KP];
__device__ __nv_bfloat16 d_Wih_lo[NROWS * KP];
__device__ __nv_bfloat16 d_Whh_hi[NROWS * KP];
__device__ __nv_bfloat16 d_Whh_lo[NROWS * KP];
__device__ float d_bp_ih[G3];
__device__ float d_bp_hh[G3];
__device__ float d_VG[(size_t)VROWS * G3];                   // vocab gates (b_ih + rz(b_hh) folded)
__device__ __nv_bfloat16 d_Hhi[(size_t)(Lv + 1) * Bv * KP];  // slice 0 = zeros
__device__ __nv_bfloat16 d_Hlo[(size_t)(Lv + 1) * Bv * KP];

// ---------------------------- helpers ---------------------------------------
__device__ __forceinline__ uint32_t smem_u32(const void* p) {
    uint32_t a;
    asm("{ .reg .u64 t; cvta.to.shared.u64 t, %1; cvt.u32.u64 %0, t; }" : "=r"(a) : "l"(p));
    return a;
}
__device__ __forceinline__ void ldsm_x4(uint32_t* r, uint32_t addr) {
    asm volatile("ldmatrix.sync.aligned.m8n8.x4.shared.b16 {%0,%1,%2,%3}, [%4];"
                 : "=r"(r[0]), "=r"(r[1]), "=r"(r[2]), "=r"(r[3]) : "r"(addr));
}
__device__ __forceinline__ void ldsm_x2(uint32_t* r, uint32_t addr) {
    asm volatile("ldmatrix.sync.aligned.m8n8.x2.shared.b16 {%0,%1}, [%2];"
                 : "=r"(r[0]), "=r"(r[1]) : "r"(addr));
}
__device__ __forceinline__ void mma_bf16(float* c, const uint32_t* a, const uint32_t* b) {
    asm volatile(
        "mma.sync.aligned.m16n8k16.row.col.f32.bf16.bf16.f32 "
        "{%0,%1,%2,%3}, {%4,%5,%6,%7}, {%8,%9}, {%0,%1,%2,%3};"
        : "+f"(c[0]), "+f"(c[1]), "+f"(c[2]), "+f"(c[3])
        : "r"(a[0]), "r"(a[1]), "r"(a[2]), "r"(a[3]), "r"(b[0]), "r"(b[1]));
}
__device__ __forceinline__ void cp16(uint32_t dst, const void* src) {
    asm volatile("cp.async.cg.shared.global [%0], [%1], 16;" :: "r"(dst), "l"(src));
}
#define CP_COMMIT() asm volatile("cp.async.commit_group;" ::: "memory")
#define CP_WAIT0()  asm volatile("cp.async.wait_group 0;" ::: "memory")
#define CP_WAIT1()  asm volatile("cp.async.wait_group 1;" ::: "memory")

// ---------------------------- conversion kernels ---------------------------
__global__ void conv_emb(const float* __restrict__ emb,
                         __nv_bfloat16* __restrict__ hi, __nv_bfloat16* __restrict__ lo)
{
    long i = (long)blockIdx.x * blockDim.x + threadIdx.x;
    if (i >= (long)VOCAB * Ev) return;
    int row = (int)(i / Ev), col = (int)(i - (long)row * Ev);
    float x = emb[i];
    __nv_bfloat16 h = __float2bfloat16(x);
    hi[(size_t)row * KP + col] = h;
    lo[(size_t)row * KP + col] = __float2bfloat16(x - __bfloat162float(h));
}

__global__ void conv_w(const float* __restrict__ W, const float* __restrict__ b,
                       __nv_bfloat16* __restrict__ hi, __nv_bfloat16* __restrict__ lo,
                       float* __restrict__ bp)
{
    int n = blockIdx.x;            // 0..899, target row = 3j+g
    int j = n / 3, g = n % 3;
    const float* src = W + (size_t)(g * Hv + j) * 300;
    for (int k = threadIdx.x; k < 300; k += blockDim.x) {
        float x = src[k];
        __nv_bfloat16 h = __float2bfloat16(x);
        hi[(size_t)n * KP + k] = h;
        lo[(size_t)n * KP + k] = __float2bfloat16(x - __bfloat162float(h));
    }
    if (threadIdx.x == 0) bp[n] = b[g * Hv + j];
}

// ---------------------------------------------------------------------------
// VG GEMM: VG = emb @ W_ih^T + b_ih + rz(b_hh). Superchunk pipeline:
// per k-chunk of 32, load Ahi/Alo/Bhi/Blo once, run 3 split passes.
// Block 128x96, 8 warps (2m x 4n), warp tile 64x24. cp.async, 2 stages.
// ---------------------------------------------------------------------------
#define V_A_HI(s) ((s) * 17920 + 0)
#define V_A_LO(s) ((s) * 17920 + 5120)
#define V_B_HI(s) ((s) * 17920 + 10240)
#define V_B_LO(s) ((s) * 17920 + 14080)
#define GH_STRIDE 100
#define SMEM_VG (2 * 17920 * 2)            // 71680 B; C epilogue aliases (51200 B)

__global__ void __launch_bounds__(256)
vg_gemm(const __nv_bfloat16* __restrict__ Ahi, const __nv_bfloat16* __restrict__ Alo,
        const __nv_bfloat16* __restrict__ Bhi, const __nv_bfloat16* __restrict__ Blo,
        const float* __restrict__ bias1, const float* __restrict__ bias2,
        float* __restrict__ VGout)
{
    extern __shared__ __align__(16) char smem[];
    float* ghs = (float*)smem;
    const uint32_t sbase = smem_u32(smem);

    int tid = threadIdx.x;
    int lane = tid & 31, wid = tid >> 5;
    int wm = wid >> 2, wn = wid & 3;
    int m0 = blockIdx.y * 128;
    int n0 = blockIdx.x * 96;

    int a_row = lane & 15, a_k = (lane >> 4) << 3;
    int b_row = lane & 7,  b_k = ((lane >> 3) & 1) << 3;

    auto load_chunk = [&](int cc, int s) {
        int kb = cc * 32;
        int r1 = tid >> 2, co = (tid & 3) * 8;
        int r2 = 64 + r1;
        cp16(sbase + (uint32_t)(V_A_HI(s) + r1 * 40 + co) * 2, Ahi + (size_t)(m0 + r1) * KP + kb + co);
        cp16(sbase + (uint32_t)(V_A_HI(s) + r2 * 40 + co) * 2, Ahi + (size_t)(m0 + r2) * KP + kb + co);
        cp16(sbase + (uint32_t)(V_A_LO(s) + r1 * 40 + co) * 2, Alo + (size_t)(m0 + r1) * KP + kb + co);
        cp16(sbase + (uint32_t)(V_A_LO(s) + r2 * 40 + co) * 2, Alo + (size_t)(m0 + r2) * KP + kb + co);
        cp16(sbase + (uint32_t)(V_B_HI(s) + r1 * 40 + co) * 2, Bhi + (size_t)(n0 + r1) * KP + kb + co);
        cp16(sbase + (uint32_t)(V_B_LO(s) + r1 * 40 + co) * 2, Blo + (size_t)(n0 + r1) * KP + kb + co);
        if (tid < 128) {
            int r3 = 64 + r1;   // rows 64..95
            cp16(sbase + (uint32_t)(V_B_HI(s) + r3 * 40 + co) * 2, Bhi + (size_t)(n0 + r3) * KP + kb + co);
            cp16(sbase + (uint32_t)(V_B_LO(s) + r3 * 40 + co) * 2, Blo + (size_t)(n0 + r3) * KP + kb + co);
        }
        CP_COMMIT();
    };

    float acc[4][3][4];
#pragma unroll
    for (int mi = 0; mi < 4; mi++)
#pragma unroll
        for (int ni = 0; ni < 3; ni++)
#pragma unroll
            for (int q = 0; q < 4; q++) acc[mi][ni][q] = 0.f;

    load_chunk(0, 0);
    load_chunk(1, 1);

    for (int c = 0; c < 10; c++) {
        if (c < 9) { CP_WAIT1(); } else { CP_WAIT0(); }
        __syncthreads();
        int s = c & 1;
        uint32_t ah = sbase + (uint32_t)V_A_HI(s) * 2;
        uint32_t al = sbase + (uint32_t)V_A_LO(s) * 2;
        uint32_t bh = sbase + (uint32_t)V_B_HI(s) * 2;
        uint32_t bl = sbase + (uint32_t)V_B_LO(s) * 2;
#pragma unroll
        for (int kk = 0; kk < 2; kk++) {
            uint32_t fah[4][4], fal[4][4], fbh[3][2], fbl[3][2];
#pragma unroll
            for (int mi = 0; mi < 4; mi++) {
                uint32_t ro = (uint32_t)((wm * 64 + mi * 16 + a_row) * 40 + kk * 16 + a_k) * 2;
                ldsm_x4(fah[mi], ah + ro);
                ldsm_x4(fal[mi], al + ro);
            }
#pragma unroll
            for (int ni = 0; ni < 3; ni++) {
                uint32_t ro = (uint32_t)((wn * 24 + ni * 8 + b_row) * 40 + kk * 16 + b_k) * 2;
                ldsm_x2(fbh[ni], bh + ro);
                ldsm_x2(fbl[ni], bl + ro);
            }
#pragma unroll
            for (int mi = 0; mi < 4; mi++)
#pragma unroll
                for (int ni = 0; ni < 3; ni++) {
                    mma_bf16(acc[mi][ni], fah[mi], fbh[ni]);
                    mma_bf16(acc[mi][ni], fal[mi], fbh[ni]);
                    mma_bf16(acc[mi][ni], fah[mi], fbl[ni]);
                }
        }
        __syncthreads();
        if (c + 2 < 10) load_chunk(c + 2, s);
    }

#pragma unroll
    for (int mi = 0; mi < 4; mi++) {
        int mr = wm * 64 + mi * 16 + (lane >> 2);
#pragma unroll
        for (int ni = 0; ni < 3; ni++) {
            int nn = wn * 24 + ni * 8 + (lane & 3) * 2;
            ghs[mr * GH_STRIDE + nn]           = acc[mi][ni][0];
            ghs[mr * GH_STRIDE + nn + 1]       = acc[mi][ni][1];
            ghs[(mr + 8) * GH_STRIDE + nn]     = acc[mi][ni][2];
            ghs[(mr + 8) * GH_STRIDE + nn + 1] = acc[mi][ni][3];
        }
    }
    __syncthreads();

    for (int i = tid; i < 128 * 96; i += 256) {
        int m = i / 96, n = i - m * 96;
        int gn = n0 + n;
        if (gn < G3) {
            float b2 = (gn % 3 != 2) ? bias2[gn] : 0.f;   // fold b_hh for r,z only
            VGout[(size_t)(m0 + m) * G3 + gn] = ghs[m * GH_STRIDE + n] + bias1[gn] + b2;
        }
    }
}

// ---------------------------------------------------------------------------
// GRU step: gh = h_prev @ Whh^T (3-term split, superchunk reuse) + gate fuse.
// Block 64x96, 8 warps (2m x 4n), warp tile 32x24. grid (10, 32) = 320 blocks.
// 2-stage cp.async pipeline; gx gather prefetched via cp.async at kernel start;
// h_prev for the blend read via coalesced LDG in the epilogue.
// smem: stages [0, 51200), gx fp32 [51200, 75776), bhn [75776, 75904).
// ---------------------------------------------------------------------------
#define S_A_HI(s) ((s) * 12800 + 0)
#define S_A_LO(s) ((s) * 12800 + 2560)
#define S_B_HI(s) ((s) * 12800 + 5120)
#define S_B_LO(s) ((s) * 12800 + 8960)
#define GXS_B 51200
#define BHN_B 75776
#define SMEM_STEP 75904

__global__ void __launch_bounds__(256)
gru_step(const __nv_bfloat16* __restrict__ Hp_hi, const __nv_bfloat16* __restrict__ Hp_lo,
         const __nv_bfloat16* __restrict__ Bhi, const __nv_bfloat16* __restrict__ Blo,
         const int* __restrict__ seq, const float* __restrict__ VGin,
         const float* __restrict__ bph,
         __nv_bfloat16* __restrict__ Ho_hi, __nv_bfloat16* __restrict__ Ho_lo,
         int l)
{
    extern __shared__ __align__(16) char smem[];
    float* cs  = (float*)smem;                    // epilogue C, aliases stage 0
    float* gxs = (float*)(smem + GXS_B);
    float* bhn = (float*)(smem + BHN_B);
    const uint32_t sbase = smem_u32(smem);

    int tid = threadIdx.x;
    int lane = tid & 31, wid = tid >> 5;
    int wm = wid >> 2, wn = wid & 3;
    int m0 = blockIdx.y * 64;
    int n0 = blockIdx.x * 96;
    int j0 = blockIdx.x * 32;

    // ---- gather prefetch (gx from VG, token-indexed) ----
#pragma unroll
    for (int c = 0; c < 6; c++) {
        int idx = tid + c * 256;           // 0..1535
        int row = idx / 24, off = (idx % 24) * 4;
        int t = seq[(m0 + row) * Lv + l];
        cp16(sbase + GXS_B + (uint32_t)(row * 96 + off) * 4,
             VGin + (size_t)t * G3 + n0 + off);
    }
    if (tid < 32 && (n0 + 3 * tid + 2) < G3) bhn[tid] = bph[n0 + 3 * tid + 2];
    CP_COMMIT();                            // group G

    int a_row = lane & 15, a_k = (lane >> 4) << 3;
    int b_row = lane & 7,  b_k = ((lane >> 3) & 1) << 3;

    auto load_chunk = [&](int cc, int s) {
        int kb = cc * 32;
        int r1 = tid >> 2, co = (tid & 3) * 8;
        cp16(sbase + (uint32_t)(S_A_HI(s) + r1 * 40 + co) * 2, Hp_hi + (size_t)(m0 + r1) * KP + kb + co);
        cp16(sbase + (uint32_t)(S_A_LO(s) + r1 * 40 + co) * 2, Hp_lo + (size_t)(m0 + r1) * KP + kb + co);
        cp16(sbase + (uint32_t)(S_B_HI(s) + r1 * 40 + co) * 2, Bhi + (size_t)(n0 + r1) * KP + kb + co);
        cp16(sbase + (uint32_t)(S_B_LO(s) + r1 * 40 + co) * 2, Blo + (size_t)(n0 + r1) * KP + kb + co);
        if (tid < 128) {
            int r2 = 64 + r1;               // B rows 64..95
            cp16(sbase + (uint32_t)(S_B_HI(s) + r2 * 40 + co) * 2, Bhi + (size_t)(n0 + r2) * KP + kb + co);
            cp16(sbase + (uint32_t)(S_B_LO(s) + r2 * 40 + co) * 2, Blo + (size_t)(n0 + r2) * KP + kb + co);
        }
        CP_COMMIT();
    };

    float acc[2][3][4];
#pragma unroll
    for (int mi = 0; mi < 2; mi++)
#pragma unroll
        for (int ni = 0; ni < 3; ni++)
#pragma unroll
            for (int q = 0; q < 4; q++) acc[mi][ni][q] = 0.f;

    load_chunk(0, 0);
    load_chunk(1, 1);

    for (int c = 0; c < 10; c++) {
        if (c < 9) { CP_WAIT1(); } else { CP_WAIT0(); }
        __syncthreads();
        int s = c & 1;
        uint32_t ah = sbase + (uint32_t)S_A_HI(s) * 2;
        uint32_t al = sbase + (uint32_t)S_A_LO(s) * 2;
        uint32_t bh = sbase + (uint32_t)S_B_HI(s) * 2;
        uint32_t bl = sbase + (uint32_t)S_B_LO(s) * 2;
#pragma unroll
        for (int kk = 0; kk < 2; kk++) {
            uint32_t fah[2][4], fal[2][4], fbh[3][2], fbl[3][2];
#pragma unroll
            for (int mi = 0; mi < 2; mi++) {
                uint32_t ro = (uint32_t)((wm * 32 + mi * 16 + a_row) * 40 + kk * 16 + a_k) * 2;
                ldsm_x4(fah[mi], ah + ro);
                ldsm_x4(fal[mi], al + ro);
            }
#pragma unroll
            for (int ni = 0; ni < 3; ni++) {
                uint32_t ro = (uint32_t)((wn * 24 + ni * 8 + b_row) * 40 + kk * 16 + b_k) * 2;
                ldsm_x2(fbh[ni], bh + ro);
                ldsm_x2(fbl[ni], bl + ro);
            }
#pragma unroll
            for (int mi = 0; mi < 2; mi++)
#pragma unroll
                for (int ni = 0; ni < 3; ni++) {
                    mma_bf16(acc[mi][ni], fah[mi], fbh[ni]);
                    mma_bf16(acc[mi][ni], fal[mi], fbh[ni]);
                    mma_bf16(acc[mi][ni], fah[mi], fbl[ni]);
                }
        }
        __syncthreads();
        if (c + 2 < 10) load_chunk(c + 2, s);
    }

    // ---- dump C to smem (stage region reuse; all compute synced) ----
#pragma unroll
    for (int mi = 0; mi < 2; mi++) {
        int mr = wm * 32 + mi * 16 + (lane >> 2);
#pragma unroll
        for (int ni = 0; ni < 3; ni++) {
            int nn = wn * 24 + ni * 8 + (lane & 3) * 2;
            cs[mr * GH_STRIDE + nn]           = acc[mi][ni][0];
            cs[mr * GH_STRIDE + nn + 1]       = acc[mi][ni][1];
            cs[(mr + 8) * GH_STRIDE + nn]     = acc[mi][ni][2];
            cs[(mr + 8) * GH_STRIDE + nn + 1] = acc[mi][ni][3];
        }
    }
    __syncthreads();

    // ---- gate epilogue (gx already in smem; h_prev blend via coalesced LDG) ----
    for (int i = tid; i < 64 * 32; i += 256) {
        int ml = i >> 5, p = i & 31;
        int j = j0 + p;
        if (j < Hv) {
            int m = m0 + ml;
            float gh_r = cs[ml * GH_STRIDE + 3 * p + 0];
            float gh_z = cs[ml * GH_STRIDE + 3 * p + 1];
            float gh_n = cs[ml * GH_STRIDE + 3 * p + 2] + bhn[p];  // b_hh_n inside r*(.)
            float gx_r = gxs[ml * 96 + 3 * p + 0];
            float gx_z = gxs[ml * 96 + 3 * p + 1];
            float gx_n = gxs[ml * 96 + 3 * p + 2];
            float r = 1.f / (1.f + expf(-(gx_r + gh_r)));
            float z = 1.f / (1.f + expf(-(gx_z + gh_z)));
            float ng = tanhf(gx_n + r * gh_n);
            size_t hidx = (size_t)m * KP + j;
            float hp = __bfloat162float(Hp_hi[hidx]) + __bfloat162float(Hp_lo[hidx]);
            float h = (1.f - z) * ng + z * hp;
            __nv_bfloat16 hh = __float2bfloat16(h);
            Ho_hi[hidx] = hh;
            Ho_lo[hidx] = __float2bfloat16(h - __bfloat162float(hh));
        }
    }
}

// ---------------------------------------------------------------------------
// Post: collapsed co-attention + softmax + pooling + logits.
// ---------------------------------------------------------------------------
__device__ __forceinline__ float blockReduceSum(float v, volatile float* red)
{
    __syncthreads();
#pragma unroll
    for (int o = 16; o > 0; o >>= 1) v += __shfl_xor_sync(0xffffffffu, v, o);
    int w = threadIdx.x >> 5, ln = threadIdx.x & 31;
    if (ln == 0) red[w] = v;
    __syncthreads();
    if (threadIdx.x < 32) {
        float x = (threadIdx.x < 8) ? red[threadIdx.x] : 0.f;
#pragma unroll
        for (int o = 4; o > 0; o >>= 1) x += __shfl_xor_sync(0xffffffffu, x, o);
        if (threadIdx.x == 0) red[0] = x;
    }
    __syncthreads();
    return red[0];
}
__device__ __forceinline__ float blockReduceMax(float v, volatile float* red)
{
    __syncthreads();
#pragma unroll
    for (int o = 16; o > 0; o >>= 1) v = fmaxf(v, __shfl_xor_sync(0xffffffffu, v, o));
    int w = threadIdx.x >> 5, ln = threadIdx.x & 31;
    if (ln == 0) red[w] = v;
    __syncthreads();
    if (threadIdx.x < 32) {
        float x = (threadIdx.x < 8) ? red[threadIdx.x] : -3.4e38f;
#pragma unroll
        for (int o = 4; o > 0; o >>= 1) x = fmaxf(x, __shfl_xor_sync(0xffffffffu, x, o));
        if (threadIdx.x == 0) red[0] = x;
    }
    __syncthreads();
    return red[0];
}

__global__ void post_kernel(const __nv_bfloat16* __restrict__ Hhi,
                            const __nv_bfloat16* __restrict__ Hlo,
                            const float* __restrict__ wCo_w, const float* __restrict__ wCo_b,
                            const float* __restrict__ Wmy_w, const float* __restrict__ Wmy_b,
                            const float* __restrict__ logits_w, const float* __restrict__ logits_b,
                            float* __restrict__ out)
{
    extern __shared__ float fs[];
    float* h_s    = fs;
    float* wa     = h_s + Lv * Hv;
    float* wb_    = wa + Hv;
    float* wc     = wb_ + Hv;
    float* wmy    = wc + Hv;
    float* aa     = wmy + 80;
    float* bb     = aa + 80;
    float* qq     = bb + 80;
    float* pp     = qq + 80;
    float* smarr  = pp + 80;
    float* attn   = smarr + 80;
    float* u      = attn + 80;
    float* pooled = u + Hv;
    __shared__ float red[32];

    int b = blockIdx.x;
    int tid = threadIdx.x;
    int w = tid >> 5, ln = tid & 31;

    for (int t = tid; t < Lv * Hv; t += 256) {
        int i = t / Hv, d = t - i * Hv;
        size_t idx = (size_t)(i + 1) * Bv * KP + (size_t)b * KP + d;
        h_s[t] = __bfloat162float(Hhi[idx]) + __bfloat162float(Hlo[idx]);
    }
    for (int t = tid; t < Hv; t += 256) {
        wa[t]  = wCo_w[t];
        wb_[t] = wCo_w[Hv + t];
        wc[t]  = wCo_w[2 * Hv + t];
    }
    if (tid < Lv) wmy[tid] = Wmy_w[tid];
    __syncthreads();

    for (int i = w; i < Lv; i += 8) {
        float sa = 0.f, sb2 = 0.f, sq = 0.f;
        for (int d = ln; d < Hv; d += 32) {
            float hv = h_s[i * Hv + d];
            sa += hv * wa[d];
            sb2 += hv * wb_[d];
            sq += hv * hv * wc[d];
        }
#pragma unroll
        for (int o = 16; o > 0; o >>= 1) {
            sa += __shfl_xor_sync(0xffffffffu, sa, o);
            sb2 += __shfl_xor_sync(0xffffffffu, sb2, o);
            sq += __shfl_xor_sync(0xffffffffu, sq, o);
        }
        if (ln == 0) { aa[i] = sa; bb[i] = sb2; qq[i] = sq; }
    }
    __syncthreads();

    for (int d = tid; d < Hv; d += 256) {
        float s = 0.f;
#pragma unroll 5
        for (int i = 0; i < Lv; i++) s += wmy[i] * h_s[i * Hv + d];
        u[d] = s;
    }

    float swv = (tid < Lv) ? wmy[tid] : 0.f;
    float Sw = blockReduceSum(swv, red);
    float tv = (tid < Lv) ? wmy[tid] * bb[tid] : 0.f;
    float T = blockReduceSum(tv, red);
    __syncthreads();

    for (int i = w; i < Lv; i += 8) {
        float sp = 0.f;
        for (int d = ln; d < Hv; d += 32) sp += h_s[i * Hv + d] * wc[d] * u[d];
#pragma unroll
        for (int o = 16; o > 0; o >>= 1) sp += __shfl_xor_sync(0xffffffffu, sp, o);
        if (ln == 0) pp[i] = sp;
    }
    __syncthreads();

    float beta = wCo_b[0];
    if (tid < Lv) {
        smarr[tid] = (aa[tid] + beta) * Sw + T + pp[tid]
                   - wmy[tid] * (aa[tid] + bb[tid] + beta + qq[tid]) + Wmy_b[0];
    }
    __syncthreads();

    float mv = (tid < Lv) ? smarr[tid] : -3.4e38f;
    float mx = blockReduceMax(mv, red);
    float ev = (tid < Lv) ? expf(smarr[tid] - mx) : 0.f;
    if (tid < Lv) attn[tid] = ev;
    float se = blockReduceSum(ev, red);
    if (tid < Lv) attn[tid] = attn[tid] / se;
    __syncthreads();

    for (int d = tid; d < Hv; d += 256) {
        float s = 0.f;
#pragma unroll 5
        for (int i = 0; i < Lv; i++) s += attn[i] * h_s[i * Hv + d];
        pooled[d] = s;
    }
    __syncthreads();

    if (w < OUTv) {
        float s = 0.f;
        for (int d = ln; d < Hv; d += 32) s += pooled[d] * logits_w[w * Hv + d];
#pragma unroll
        for (int o = 16; o > 0; o >>= 1) s += __shfl_xor_sync(0xffffffffu, s, o);
        if (ln == 0) out[(size_t)b * OUTv + w] = s + logits_b[w];
    }
}

// ---------------------------------------------------------------------------
extern "C" void kernel_launch(void* const* d_in, const int* in_sizes, int n_in,
                              void* d_out, int out_size)
{
    const int*   seq      = (const int*)  d_in[0];
    const float* emb      = (const float*)d_in[1];
    const float* W_ih     = (const float*)d_in[2];
    const float* W_hh     = (const float*)d_in[3];
    const float* b_ih     = (const float*)d_in[4];
    const float* b_hh     = (const float*)d_in[5];
    const float* wCo_w    = (const float*)d_in[6];
    const float* wCo_b    = (const float*)d_in[7];
    const float* Wmy_w    = (const float*)d_in[8];
    const float* Wmy_b    = (const float*)d_in[9];
    const float* logits_w = (const float*)d_in[10];
    const float* logits_b = (const float*)d_in[11];
    float* out = (float*)d_out;

    __nv_bfloat16 *ehi, *elo, *wih_hi, *wih_lo, *whh_hi, *whh_lo, *Hhi, *Hlo;
    float *bpih, *bphh, *VG;
    cudaGetSymbolAddress((void**)&ehi,    d_emb_hi);
    cudaGetSymbolAddress((void**)&elo,    d_emb_lo);
    cudaGetSymbolAddress((void**)&wih_hi, d_Wih_hi);
    cudaGetSymbolAddress((void**)&wih_lo, d_Wih_lo);
    cudaGetSymbolAddress((void**)&whh_hi, d_Whh_hi);
    cudaGetSymbolAddress((void**)&whh_lo, d_Whh_lo);
    cudaGetSymbolAddress((void**)&bpih,   d_bp_ih);
    cudaGetSymbolAddress((void**)&bphh,   d_bp_hh);
    cudaGetSymbolAddress((void**)&VG,     d_VG);
    cudaGetSymbolAddress((void**)&Hhi,    d_Hhi);
    cudaGetSymbolAddress((void**)&Hlo,    d_Hlo);

    cudaFuncSetAttribute(vg_gemm, cudaFuncAttributeMaxDynamicSharedMemorySize, SMEM_VG);
    cudaFuncSetAttribute(gru_step, cudaFuncAttributeMaxDynamicSharedMemorySize, SMEM_STEP);
    const int POST_SMEM = (Lv * Hv + 3 * Hv + 7 * 80 + 2 * Hv) * (int)sizeof(float);
    cudaFuncSetAttribute(post_kernel, cudaFuncAttributeMaxDynamicSharedMemorySize, POST_SMEM);

    // 0) conversions: emb -> bf16 hi/lo (padded), weights permuted+split
    {
        long n = (long)VOCAB * Ev;
        conv_emb<<<(unsigned)((n + 255) / 256), 256>>>(emb, ehi, elo);
    }
    conv_w<<<G3, 128>>>(W_ih, b_ih, wih_hi, wih_lo, bpih);
    conv_w<<<G3, 128>>>(W_hh, b_hh, whh_hi, whh_lo, bphh);

    // 1) VG = emb @ W_ih^T + b_ih + rz(b_hh) over full vocab
    {
        dim3 grid(10, VROWS / 128);
        vg_gemm<<<grid, 256, SMEM_VG>>>(ehi, elo, wih_hi, wih_lo, bpih, bphh, VG);
    }

    // 2) GRU recurrence: 75 fused steps
    const size_t slice = (size_t)Bv * KP;
    for (int l = 0; l < Lv; l++) {
        dim3 grid(10, Bv / 64);
        gru_step<<<grid, 256, SMEM_STEP>>>(Hhi + (size_t)l * slice, Hlo + (size_t)l * slice,
                                           whh_hi, whh_lo,
                                           seq, VG, bphh,
                                           Hhi + (size_t)(l + 1) * slice, Hlo + (size_t)(l + 1) * slice,
                                           l);
    }

    // 3) collapsed co-attention + softmax + pooling + logits
    post_kernel<<<Bv, 256, POST_SMEM>>>(Hhi, Hlo, wCo_w, wCo_b, Wmy_w, Wmy_b,
                                        logits_w, logits_b, out);
}

// round 8
// speedup vs baseline: 5.0439x; 1.0264x over previous
#include <cuda_runtime.h>
#include <cuda_bf16.h>
#include <math.h>
#include <stdint.h>

#define Bv   2048
#define Lv   75
#define Ev   300
#define Hv   300
#define G3   900
#define OUTv 5
#define KP   320                 // K padded to 10 x 32
#define VROWS 50048              // vocab rows padded to 391*128
#define NROWS 960                // gate rows padded to 10*96
#define VOCAB 50000
#define NTILE 10                 // n-blocks per step
#define MTILE 32                 // m-blocks per step

// ---------------- scratch (device globals; zero-initialized) ---------------
__device__ __nv_bfloat16 d_emb_hi[(size_t)VROWS * KP];
__device__ __nv_bfloat16 d_emb_lo[(size_t)VROWS * KP];
__device__ __nv_bfloat16 d_Wih_hi[NROWS * KP];
__device__ __nv_bfloat16 d_Wih_lo[NROWS * KP];
__device__ __nv_bfloat16 d_Whh_hi[NROWS * KP];
__device__ __nv_bfloat16 d_Whh_lo[NROWS * KP];
__device__ float d_bp_ih[G3];
__device__ float d_bp_hh[G3];
__device__ float d_VG[(size_t)VROWS * G3];                   // vocab gates (b_ih + rz(b_hh) folded)
__device__ __nv_bfloat16 d_Hhi[(size_t)(Lv + 1) * Bv * KP];  // slice 0 = zeros
__device__ __nv_bfloat16 d_Hlo[(size_t)(Lv + 1) * Bv * KP];
__device__ unsigned int d_flag[Lv][MTILE];                   // producers of slice s+1
__device__ unsigned int d_done[MTILE];

// ---------------------------- helpers ---------------------------------------
__device__ __forceinline__ uint32_t smem_u32(const void* p) {
    uint32_t a;
    asm("{ .reg .u64 t; cvta.to.shared.u64 t, %1; cvt.u32.u64 %0, t; }" : "=r"(a) : "l"(p));
    return a;
}
__device__ __forceinline__ void ldsm_x4(uint32_t* r, uint32_t addr) {
    asm volatile("ldmatrix.sync.aligned.m8n8.x4.shared.b16 {%0,%1,%2,%3}, [%4];"
                 : "=r"(r[0]), "=r"(r[1]), "=r"(r[2]), "=r"(r[3]) : "r"(addr));
}
__device__ __forceinline__ void ldsm_x2(uint32_t* r, uint32_t addr) {
    asm volatile("ldmatrix.sync.aligned.m8n8.x2.shared.b16 {%0,%1}, [%2];"
                 : "=r"(r[0]), "=r"(r[1]) : "r"(addr));
}
__device__ __forceinline__ void mma_bf16(float* c, const uint32_t* a, const uint32_t* b) {
    asm volatile(
        "mma.sync.aligned.m16n8k16.row.col.f32.bf16.bf16.f32 "
        "{%0,%1,%2,%3}, {%4,%5,%6,%7}, {%8,%9}, {%0,%1,%2,%3};"
        : "+f"(c[0]), "+f"(c[1]), "+f"(c[2]), "+f"(c[3])
        : "r"(a[0]), "r"(a[1]), "r"(a[2]), "r"(a[3]), "r"(b[0]), "r"(b[1]));
}
__device__ __forceinline__ void cp16(uint32_t dst, const void* src) {
    asm volatile("cp.async.cg.shared.global [%0], [%1], 16;" :: "r"(dst), "l"(src));
}
#define CP_COMMIT() asm volatile("cp.async.commit_group;" ::: "memory")
#define CP_WAIT0()  asm volatile("cp.async.wait_group 0;" ::: "memory")
#define CP_WAIT1()  asm volatile("cp.async.wait_group 1;" ::: "memory")

__device__ __forceinline__ unsigned int ld_acq(const unsigned int* p) {
    unsigned int v;
    asm volatile("ld.global.acquire.gpu.u32 %0, [%1];" : "=r"(v) : "l"(p) : "memory");
    return v;
}
__device__ __forceinline__ void red_rel_add1(unsigned int* p) {
    asm volatile("red.release.gpu.global.add.u32 [%0], 1;" :: "l"(p) : "memory");
}

// ---------------------------- conversion kernels ---------------------------
__global__ void conv_emb(const float* __restrict__ emb,
                         __nv_bfloat16* __restrict__ hi, __nv_bfloat16* __restrict__ lo)
{
    long i = (long)blockIdx.x * blockDim.x + threadIdx.x;
    if (i >= (long)VOCAB * Ev) return;
    int row = (int)(i / Ev), col = (int)(i - (long)row * Ev);
    float x = emb[i];
    __nv_bfloat16 h = __float2bfloat16(x);
    hi[(size_t)row * KP + col] = h;
    lo[(size_t)row * KP + col] = __float2bfloat16(x - __bfloat162float(h));
}

__global__ void conv_w(const float* __restrict__ W, const float* __restrict__ b,
                       __nv_bfloat16* __restrict__ hi, __nv_bfloat16* __restrict__ lo,
                       float* __restrict__ bp)
{
    int n = blockIdx.x;            // 0..899, target row = 3j+g
    int j = n / 3, g = n % 3;
    const float* src = W + (size_t)(g * Hv + j) * 300;
    for (int k = threadIdx.x; k < 300; k += blockDim.x) {
        float x = src[k];
        __nv_bfloat16 h = __float2bfloat16(x);
        hi[(size_t)n * KP + k] = h;
        lo[(size_t)n * KP + k] = __float2bfloat16(x - __bfloat162float(h));
    }
    if (threadIdx.x == 0) bp[n] = b[g * Hv + j];
}

// ---------------------------------------------------------------------------
// VG GEMM: VG = emb @ W_ih^T + b_ih + rz(b_hh). Superchunk 4-plane pipeline.
// Block 128x96, 8 warps (2m x 4n), warp tile 64x24. cp.async, 2 stages.
// ---------------------------------------------------------------------------
#define V_A_HI(s) ((s) * 17920 + 0)
#define V_A_LO(s) ((s) * 17920 + 5120)
#define V_B_HI(s) ((s) * 17920 + 10240)
#define V_B_LO(s) ((s) * 17920 + 14080)
#define GH_STRIDE 100
#define SMEM_VG (2 * 17920 * 2)

__global__ void __launch_bounds__(256)
vg_gemm(const __nv_bfloat16* __restrict__ Ahi, const __nv_bfloat16* __restrict__ Alo,
        const __nv_bfloat16* __restrict__ Bhi, const __nv_bfloat16* __restrict__ Blo,
        const float* __restrict__ bias1, const float* __restrict__ bias2,
        float* __restrict__ VGout)
{
    extern __shared__ __align__(16) char smem[];
    float* ghs = (float*)smem;
    const uint32_t sbase = smem_u32(smem);

    int tid = threadIdx.x;
    int lane = tid & 31, wid = tid >> 5;
    int wm = wid >> 2, wn = wid & 3;
    int m0 = blockIdx.y * 128;
    int n0 = blockIdx.x * 96;

    int a_row = lane & 15, a_k = (lane >> 4) << 3;
    int b_row = lane & 7,  b_k = ((lane >> 3) & 1) << 3;

    auto load_chunk = [&](int cc, int s) {
        int kb = cc * 32;
        int r1 = tid >> 2, co = (tid & 3) * 8;
        int r2 = 64 + r1;
        cp16(sbase + (uint32_t)(V_A_HI(s) + r1 * 40 + co) * 2, Ahi + (size_t)(m0 + r1) * KP + kb + co);
        cp16(sbase + (uint32_t)(V_A_HI(s) + r2 * 40 + co) * 2, Ahi + (size_t)(m0 + r2) * KP + kb + co);
        cp16(sbase + (uint32_t)(V_A_LO(s) + r1 * 40 + co) * 2, Alo + (size_t)(m0 + r1) * KP + kb + co);
        cp16(sbase + (uint32_t)(V_A_LO(s) + r2 * 40 + co) * 2, Alo + (size_t)(m0 + r2) * KP + kb + co);
        cp16(sbase + (uint32_t)(V_B_HI(s) + r1 * 40 + co) * 2, Bhi + (size_t)(n0 + r1) * KP + kb + co);
        cp16(sbase + (uint32_t)(V_B_LO(s) + r1 * 40 + co) * 2, Blo + (size_t)(n0 + r1) * KP + kb + co);
        if (tid < 128) {
            int r3 = 64 + r1;
            cp16(sbase + (uint32_t)(V_B_HI(s) + r3 * 40 + co) * 2, Bhi + (size_t)(n0 + r3) * KP + kb + co);
            cp16(sbase + (uint32_t)(V_B_LO(s) + r3 * 40 + co) * 2, Blo + (size_t)(n0 + r3) * KP + kb + co);
        }
        CP_COMMIT();
    };

    float acc[4][3][4];
#pragma unroll
    for (int mi = 0; mi < 4; mi++)
#pragma unroll
        for (int ni = 0; ni < 3; ni++)
#pragma unroll
            for (int q = 0; q < 4; q++) acc[mi][ni][q] = 0.f;

    load_chunk(0, 0);
    load_chunk(1, 1);

    for (int c = 0; c < 10; c++) {
        if (c < 9) { CP_WAIT1(); } else { CP_WAIT0(); }
        __syncthreads();
        int s = c & 1;
        uint32_t ah = sbase + (uint32_t)V_A_HI(s) * 2;
        uint32_t al = sbase + (uint32_t)V_A_LO(s) * 2;
        uint32_t bh = sbase + (uint32_t)V_B_HI(s) * 2;
        uint32_t bl = sbase + (uint32_t)V_B_LO(s) * 2;
#pragma unroll
        for (int kk = 0; kk < 2; kk++) {
            uint32_t fah[4][4], fal[4][4], fbh[3][2], fbl[3][2];
#pragma unroll
            for (int mi = 0; mi < 4; mi++) {
                uint32_t ro = (uint32_t)((wm * 64 + mi * 16 + a_row) * 40 + kk * 16 + a_k) * 2;
                ldsm_x4(fah[mi], ah + ro);
                ldsm_x4(fal[mi], al + ro);
            }
#pragma unroll
            for (int ni = 0; ni < 3; ni++) {
                uint32_t ro = (uint32_t)((wn * 24 + ni * 8 + b_row) * 40 + kk * 16 + b_k) * 2;
                ldsm_x2(fbh[ni], bh + ro);
                ldsm_x2(fbl[ni], bl + ro);
            }
#pragma unroll
            for (int mi = 0; mi < 4; mi++)
#pragma unroll
                for (int ni = 0; ni < 3; ni++) {
                    mma_bf16(acc[mi][ni], fah[mi], fbh[ni]);
                    mma_bf16(acc[mi][ni], fal[mi], fbh[ni]);
                    mma_bf16(acc[mi][ni], fah[mi], fbl[ni]);
                }
        }
        __syncthreads();
        if (c + 2 < 10) load_chunk(c + 2, s);
    }

#pragma unroll
    for (int mi = 0; mi < 4; mi++) {
        int mr = wm * 64 + mi * 16 + (lane >> 2);
#pragma unroll
        for (int ni = 0; ni < 3; ni++) {
            int nn = wn * 24 + ni * 8 + (lane & 3) * 2;
            ghs[mr * GH_STRIDE + nn]           = acc[mi][ni][0];
            ghs[mr * GH_STRIDE + nn + 1]       = acc[mi][ni][1];
            ghs[(mr + 8) * GH_STRIDE + nn]     = acc[mi][ni][2];
            ghs[(mr + 8) * GH_STRIDE + nn + 1] = acc[mi][ni][3];
        }
    }
    __syncthreads();

    for (int i = tid; i < 128 * 96; i += 256) {
        int m = i / 96, n = i - m * 96;
        int gn = n0 + n;
        if (gn < G3) {
            float b2 = (gn % 3 != 2) ? bias2[gn] : 0.f;   // fold b_hh for r,z only
            VGout[(size_t)(m0 + m) * G3 + gn] = ghs[m * GH_STRIDE + n] + bias1[gn] + b2;
        }
    }
}

// ---------------------------------------------------------------------------
// GRU steps, persistent: each of 320 blocks owns tile (m,n) and loops over
// steps [s_begin, s_end). Per-m dataflow sync via release counters.
// Block 64x96, 8 warps, warp tile 32x24. __launch_bounds__(256,3) so all 320
// blocks are co-resident (required when use_flags=1).
// ---------------------------------------------------------------------------
#define S_A_HI(s) ((s) * 12800 + 0)
#define S_A_LO(s) ((s) * 12800 + 2560)
#define S_B_HI(s) ((s) * 12800 + 5120)
#define S_B_LO(s) ((s) * 12800 + 8960)
#define GXS_B 51200
#define BHN_B 75776
#define SMEM_STEP 75904

__global__ void __launch_bounds__(256, 3)
gru_persist(const __nv_bfloat16* __restrict__ Hhi_all, const __nv_bfloat16* __restrict__ Hlo_all,
            const __nv_bfloat16* __restrict__ Bhi, const __nv_bfloat16* __restrict__ Blo,
            const int* __restrict__ seq, const float* __restrict__ VGin,
            const float* __restrict__ bph,
            int s_begin, int s_end, int use_flags)
{
    extern __shared__ __align__(16) char smem[];
    float* cs  = (float*)smem;                    // epilogue C, aliases stage 0
    float* gxs = (float*)(smem + GXS_B);
    float* bhn = (float*)(smem + BHN_B);
    const uint32_t sbase = smem_u32(smem);

    int tid = threadIdx.x;
    int lane = tid & 31, wid = tid >> 5;
    int wm = wid >> 2, wn = wid & 3;
    int bn = blockIdx.x;                          // 0..9
    int bm = blockIdx.y;                          // 0..31
    int m0 = bm * 64;
    int n0 = bn * 96;
    int j0 = bn * 32;

    if (tid < 32 && (n0 + 3 * tid + 2) < G3) bhn[tid] = bph[n0 + 3 * tid + 2];

    int a_row = lane & 15, a_k = (lane >> 4) << 3;
    int b_row = lane & 7,  b_k = ((lane >> 3) & 1) << 3;
    const size_t slice = (size_t)Bv * KP;

    for (int s = s_begin; s < s_end; s++) {
        const __nv_bfloat16* Hp_hi = Hhi_all + (size_t)s * slice;
        const __nv_bfloat16* Hp_lo = Hlo_all + (size_t)s * slice;
        __nv_bfloat16* Ho_hi = (__nv_bfloat16*)(Hhi_all + (size_t)(s + 1) * slice);
        __nv_bfloat16* Ho_lo = (__nv_bfloat16*)(Hlo_all + (size_t)(s + 1) * slice);

        // ---- gx gather for this step (flag-independent; issue before wait) --
#pragma unroll
        for (int c = 0; c < 6; c++) {
            int idx = tid + c * 256;
            int row = idx / 24, off = (idx % 24) * 4;
            int t = seq[(m0 + row) * Lv + s];
            cp16(sbase + GXS_B + (uint32_t)(row * 96 + off) * 4,
                 VGin + (size_t)t * G3 + n0 + off);
        }
        CP_COMMIT();

        // ---- wait for the 10 producers of slice s (rows m-range) ----
        if (use_flags && s > 0) {
            if (tid == 0) {
                while (ld_acq(&d_flag[s - 1][bm]) < (unsigned)NTILE) __nanosleep(64);
            }
        }
        __syncthreads();

        auto load_chunk = [&](int cc, int st) {
            int kb = cc * 32;
            int r1 = tid >> 2, co = (tid & 3) * 8;
            cp16(sbase + (uint32_t)(S_A_HI(st) + r1 * 40 + co) * 2, Hp_hi + (size_t)(m0 + r1) * KP + kb + co);
            cp16(sbase + (uint32_t)(S_A_LO(st) + r1 * 40 + co) * 2, Hp_lo + (size_t)(m0 + r1) * KP + kb + co);
            cp16(sbase + (uint32_t)(S_B_HI(st) + r1 * 40 + co) * 2, Bhi + (size_t)(n0 + r1) * KP + kb + co);
            cp16(sbase + (uint32_t)(S_B_LO(st) + r1 * 40 + co) * 2, Blo + (size_t)(n0 + r1) * KP + kb + co);
            if (tid < 128) {
                int r2 = 64 + r1;
                cp16(sbase + (uint32_t)(S_B_HI(st) + r2 * 40 + co) * 2, Bhi + (size_t)(n0 + r2) * KP + kb + co);
                cp16(sbase + (uint32_t)(S_B_LO(st) + r2 * 40 + co) * 2, Blo + (size_t)(n0 + r2) * KP + kb + co);
            }
            CP_COMMIT();
        };

        float acc[2][3][4];
#pragma unroll
        for (int mi = 0; mi < 2; mi++)
#pragma unroll
            for (int ni = 0; ni < 3; ni++)
#pragma unroll
                for (int q = 0; q < 4; q++) acc[mi][ni][q] = 0.f;

        load_chunk(0, 0);
        load_chunk(1, 1);

        for (int c = 0; c < 10; c++) {
            if (c < 9) { CP_WAIT1(); } else { CP_WAIT0(); }
            __syncthreads();
            int st = c & 1;
            uint32_t ah = sbase + (uint32_t)S_A_HI(st) * 2;
            uint32_t al = sbase + (uint32_t)S_A_LO(st) * 2;
            uint32_t bh = sbase + (uint32_t)S_B_HI(st) * 2;
            uint32_t bl = sbase + (uint32_t)S_B_LO(st) * 2;
#pragma unroll
            for (int kk = 0; kk < 2; kk++) {
                uint32_t fah[2][4], fal[2][4], fbh[3][2], fbl[3][2];
#pragma unroll
                for (int mi = 0; mi < 2; mi++) {
                    uint32_t ro = (uint32_t)((wm * 32 + mi * 16 + a_row) * 40 + kk * 16 + a_k) * 2;
                    ldsm_x4(fah[mi], ah + ro);
                    ldsm_x4(fal[mi], al + ro);
                }
#pragma unroll
                for (int ni = 0; ni < 3; ni++) {
                    uint32_t ro = (uint32_t)((wn * 24 + ni * 8 + b_row) * 40 + kk * 16 + b_k) * 2;
                    ldsm_x2(fbh[ni], bh + ro);
                    ldsm_x2(fbl[ni], bl + ro);
                }
#pragma unroll
                for (int mi = 0; mi < 2; mi++)
#pragma unroll
                    for (int ni = 0; ni < 3; ni++) {
                        mma_bf16(acc[mi][ni], fah[mi], fbh[ni]);
                        mma_bf16(acc[mi][ni], fal[mi], fbh[ni]);
                        mma_bf16(acc[mi][ni], fah[mi], fbl[ni]);
                    }
            }
            __syncthreads();
            if (c + 2 < 10) load_chunk(c + 2, st);
        }

        // ---- dump C to smem (stage region; all compute synced) ----
#pragma unroll
        for (int mi = 0; mi < 2; mi++) {
            int mr = wm * 32 + mi * 16 + (lane >> 2);
#pragma unroll
            for (int ni = 0; ni < 3; ni++) {
                int nn = wn * 24 + ni * 8 + (lane & 3) * 2;
                cs[mr * GH_STRIDE + nn]           = acc[mi][ni][0];
                cs[mr * GH_STRIDE + nn + 1]       = acc[mi][ni][1];
                cs[(mr + 8) * GH_STRIDE + nn]     = acc[mi][ni][2];
                cs[(mr + 8) * GH_STRIDE + nn + 1] = acc[mi][ni][3];
            }
        }
        __syncthreads();

        // ---- gate epilogue ----
        for (int i = tid; i < 64 * 32; i += 256) {
            int ml = i >> 5, p = i & 31;
            int j = j0 + p;
            if (j < Hv) {
                int m = m0 + ml;
                float gh_r = cs[ml * GH_STRIDE + 3 * p + 0];
                float gh_z = cs[ml * GH_STRIDE + 3 * p + 1];
                float gh_n = cs[ml * GH_STRIDE + 3 * p + 2] + bhn[p];
                float gx_r = gxs[ml * 96 + 3 * p + 0];
                float gx_z = gxs[ml * 96 + 3 * p + 1];
                float gx_n = gxs[ml * 96 + 3 * p + 2];
                float r = 1.f / (1.f + expf(-(gx_r + gh_r)));
                float z = 1.f / (1.f + expf(-(gx_z + gh_z)));
                float ng = tanhf(gx_n + r * gh_n);
                size_t hidx = (size_t)m * KP + j;
                float hp = __bfloat162float(Hp_hi[hidx]) + __bfloat162float(Hp_lo[hidx]);
                float h = (1.f - z) * ng + z * hp;
                __nv_bfloat16 hh = __float2bfloat16(h);
                Ho_hi[hidx] = hh;
                Ho_lo[hidx] = __float2bfloat16(h - __bfloat162float(hh));
            }
        }

        if (use_flags) {
            __threadfence();
            __syncthreads();
            if (tid == 0) red_rel_add1(&d_flag[s][bm]);
        } else {
            __syncthreads();   // keep smem reuse safe across loop (single-step mode exits anyway)
        }
    }

    // ---- reset phase (persistent mode only): make counters replay-safe ----
    if (use_flags) {
        if (tid == 0) red_rel_add1(&d_done[bm]);
        if (bn == 0) {
            if (tid == 0) {
                while (ld_acq(&d_done[bm]) < (unsigned)NTILE) __nanosleep(64);
            }
            __syncthreads();
            for (int s = tid; s < Lv; s += 256) d_flag[s][bm] = 0;
            if (tid == 0) d_done[bm] = 0;
            __threadfence();
        }
    }
}

// ---------------------------------------------------------------------------
// Post: collapsed co-attention + softmax + pooling + logits.
// ---------------------------------------------------------------------------
__device__ __forceinline__ float blockReduceSum(float v, volatile float* red)
{
    __syncthreads();
#pragma unroll
    for (int o = 16; o > 0; o >>= 1) v += __shfl_xor_sync(0xffffffffu, v, o);
    int w = threadIdx.x >> 5, ln = threadIdx.x & 31;
    if (ln == 0) red[w] = v;
    __syncthreads();
    if (threadIdx.x < 32) {
        float x = (threadIdx.x < 8) ? red[threadIdx.x] : 0.f;
#pragma unroll
        for (int o = 4; o > 0; o >>= 1) x += __shfl_xor_sync(0xffffffffu, x, o);
        if (threadIdx.x == 0) red[0] = x;
    }
    __syncthreads();
    return red[0];
}
__device__ __forceinline__ float blockReduceMax(float v, volatile float* red)
{
    __syncthreads();
#pragma unroll
    for (int o = 16; o > 0; o >>= 1) v = fmaxf(v, __shfl_xor_sync(0xffffffffu, v, o));
    int w = threadIdx.x >> 5, ln = threadIdx.x & 31;
    if (ln == 0) red[w] = v;
    __syncthreads();
    if (threadIdx.x < 32) {
        float x = (threadIdx.x < 8) ? red[threadIdx.x] : -3.4e38f;
#pragma unroll
        for (int o = 4; o > 0; o >>= 1) x = fmaxf(x, __shfl_xor_sync(0xffffffffu, x, o));
        if (threadIdx.x == 0) red[0] = x;
    }
    __syncthreads();
    return red[0];
}

__global__ void post_kernel(const __nv_bfloat16* __restrict__ Hhi,
                            const __nv_bfloat16* __restrict__ Hlo,
                            const float* __restrict__ wCo_w, const float* __restrict__ wCo_b,
                            const float* __restrict__ Wmy_w, const float* __restrict__ Wmy_b,
                            const float* __restrict__ logits_w, const float* __restrict__ logits_b,
                            float* __restrict__ out)
{
    extern __shared__ float fs[];
    float* h_s    = fs;
    float* wa     = h_s + Lv * Hv;
    float* wb_    = wa + Hv;
    float* wc     = wb_ + Hv;
    float* wmy    = wc + Hv;
    float* aa     = wmy + 80;
    float* bb     = aa + 80;
    float* qq     = bb + 80;
    float* pp     = qq + 80;
    float* smarr  = pp + 80;
    float* attn   = smarr + 80;
    float* u      = attn + 80;
    float* pooled = u + Hv;
    __shared__ float red[32];

    int b = blockIdx.x;
    int tid = threadIdx.x;
    int w = tid >> 5, ln = tid & 31;

    for (int t = tid; t < Lv * Hv; t += 256) {
        int i = t / Hv, d = t - i * Hv;
        size_t idx = (size_t)(i + 1) * Bv * KP + (size_t)b * KP + d;
        h_s[t] = __bfloat162float(Hhi[idx]) + __bfloat162float(Hlo[idx]);
    }
    for (int t = tid; t < Hv; t += 256) {
        wa[t]  = wCo_w[t];
        wb_[t] = wCo_w[Hv + t];
        wc[t]  = wCo_w[2 * Hv + t];
    }
    if (tid < Lv) wmy[tid] = Wmy_w[tid];
    __syncthreads();

    for (int i = w; i < Lv; i += 8) {
        float sa = 0.f, sb2 = 0.f, sq = 0.f;
        for (int d = ln; d < Hv; d += 32) {
            float hv = h_s[i * Hv + d];
            sa += hv * wa[d];
            sb2 += hv * wb_[d];
            sq += hv * hv * wc[d];
        }
#pragma unroll
        for (int o = 16; o > 0; o >>= 1) {
            sa += __shfl_xor_sync(0xffffffffu, sa, o);
            sb2 += __shfl_xor_sync(0xffffffffu, sb2, o);
            sq += __shfl_xor_sync(0xffffffffu, sq, o);
        }
        if (ln == 0) { aa[i] = sa; bb[i] = sb2; qq[i] = sq; }
    }
    __syncthreads();

    for (int d = tid; d < Hv; d += 256) {
        float s = 0.f;
#pragma unroll 5
        for (int i = 0; i < Lv; i++) s += wmy[i] * h_s[i * Hv + d];
        u[d] = s;
    }

    float swv = (tid < Lv) ? wmy[tid] : 0.f;
    float Sw = blockReduceSum(swv, red);
    float tv = (tid < Lv) ? wmy[tid] * bb[tid] : 0.f;
    float T = blockReduceSum(tv, red);
    __syncthreads();

    for (int i = w; i < Lv; i += 8) {
        float sp = 0.f;
        for (int d = ln; d < Hv; d += 32) sp += h_s[i * Hv + d] * wc[d] * u[d];
#pragma unroll
        for (int o = 16; o > 0; o >>= 1) sp += __shfl_xor_sync(0xffffffffu, sp, o);
        if (ln == 0) pp[i] = sp;
    }
    __syncthreads();

    float beta = wCo_b[0];
    if (tid < Lv) {
        smarr[tid] = (aa[tid] + beta) * Sw + T + pp[tid]
                   - wmy[tid] * (aa[tid] + bb[tid] + beta + qq[tid]) + Wmy_b[0];
    }
    __syncthreads();

    float mv = (tid < Lv) ? smarr[tid] : -3.4e38f;
    float mx = blockReduceMax(mv, red);
    float ev = (tid < Lv) ? expf(smarr[tid] - mx) : 0.f;
    if (tid < Lv) attn[tid] = ev;
    float se = blockReduceSum(ev, red);
    if (tid < Lv) attn[tid] = attn[tid] / se;
    __syncthreads();

    for (int d = tid; d < Hv; d += 256) {
        float s = 0.f;
#pragma unroll 5
        for (int i = 0; i < Lv; i++) s += attn[i] * h_s[i * Hv + d];
        pooled[d] = s;
    }
    __syncthreads();

    if (w < OUTv) {
        float s = 0.f;
        for (int d = ln; d < Hv; d += 32) s += pooled[d] * logits_w[w * Hv + d];
#pragma unroll
        for (int o = 16; o > 0; o >>= 1) s += __shfl_xor_sync(0xffffffffu, s, o);
        if (ln == 0) out[(size_t)b * OUTv + w] = s + logits_b[w];
    }
}

// ---------------------------------------------------------------------------
extern "C" void kernel_launch(void* const* d_in, const int* in_sizes, int n_in,
                              void* d_out, int out_size)
{
    const int*   seq      = (const int*)  d_in[0];
    const float* emb      = (const float*)d_in[1];
    const float* W_ih     = (const float*)d_in[2];
    const float* W_hh     = (const float*)d_in[3];
    const float* b_ih     = (const float*)d_in[4];
    const float* b_hh     = (const float*)d_in[5];
    const float* wCo_w    = (const float*)d_in[6];
    const float* wCo_b    = (const float*)d_in[7];
    const float* Wmy_w    = (const float*)d_in[8];
    const float* Wmy_b    = (const float*)d_in[9];
    const float* logits_w = (const float*)d_in[10];
    const float* logits_b = (const float*)d_in[11];
    float* out = (float*)d_out;

    __nv_bfloat16 *ehi, *elo, *wih_hi, *wih_lo, *whh_hi, *whh_lo, *Hhi, *Hlo;
    float *bpih, *bphh, *VG;
    cudaGetSymbolAddress((void**)&ehi,    d_emb_hi);
    cudaGetSymbolAddress((void**)&elo,    d_emb_lo);
    cudaGetSymbolAddress((void**)&wih_hi, d_Wih_hi);
    cudaGetSymbolAddress((void**)&wih_lo, d_Wih_lo);
    cudaGetSymbolAddress((void**)&whh_hi, d_Whh_hi);
    cudaGetSymbolAddress((void**)&whh_lo, d_Whh_lo);
    cudaGetSymbolAddress((void**)&bpih,   d_bp_ih);
    cudaGetSymbolAddress((void**)&bphh,   d_bp_hh);
    cudaGetSymbolAddress((void**)&VG,     d_VG);
    cudaGetSymbolAddress((void**)&Hhi,    d_Hhi);
    cudaGetSymbolAddress((void**)&Hlo,    d_Hlo);

    cudaFuncSetAttribute(vg_gemm, cudaFuncAttributeMaxDynamicSharedMemorySize, SMEM_VG);
    cudaFuncSetAttribute(gru_persist, cudaFuncAttributeMaxDynamicSharedMemorySize, SMEM_STEP);
    const int POST_SMEM = (Lv * Hv + 3 * Hv + 7 * 80 + 2 * Hv) * (int)sizeof(float);
    cudaFuncSetAttribute(post_kernel, cudaFuncAttributeMaxDynamicSharedMemorySize, POST_SMEM);

    // Decide persistent vs per-step safely (deterministic host-side query).
    int occ = 0, sms = 0;
    cudaOccupancyMaxActiveBlocksPerMultiprocessor(&occ, gru_persist, 256, SMEM_STEP);
    cudaDeviceGetAttribute(&sms, cudaDevAttrMultiProcessorCount, 0);
    bool persistent = ((long)occ * sms >= NTILE * MTILE);

    // 0) conversions
    {
        long n = (long)VOCAB * Ev;
        conv_emb<<<(unsigned)((n + 255) / 256), 256>>>(emb, ehi, elo);
    }
    conv_w<<<G3, 128>>>(W_ih, b_ih, wih_hi, wih_lo, bpih);
    conv_w<<<G3, 128>>>(W_hh, b_hh, whh_hi, whh_lo, bphh);

    // 1) VG = emb @ W_ih^T + b_ih + rz(b_hh) over full vocab
    {
        dim3 grid(10, VROWS / 128);
        vg_gemm<<<grid, 256, SMEM_VG>>>(ehi, elo, wih_hi, wih_lo, bpih, bphh, VG);
    }

    // 2) GRU recurrence
    dim3 grid(NTILE, MTILE);
    if (persistent) {
        gru_persist<<<grid, 256, SMEM_STEP>>>(Hhi, Hlo, whh_hi, whh_lo,
                                              seq, VG, bphh, 0, Lv, 1);
    } else {
        for (int l = 0; l < Lv; l++)
            gru_persist<<<grid, 256, SMEM_STEP>>>(Hhi, Hlo, whh_hi, whh_lo,
                                                  seq, VG, bphh, l, l + 1, 0);
    }

    // 3) collapsed co-attention + softmax + pooling + logits
    post_kernel<<<Bv, 256, POST_SMEM>>>(Hhi, Hlo, wCo_w, wCo_b, Wmy_w, Wmy_b,
                                        logits_w, logits_b, out);
}